// round 3
// baseline (speedup 1.0000x reference)
#include <cuda_runtime.h>
#include <math.h>

// ---------------- problem constants ----------------
#define BATCH 8
#define SEQ   2048
#define DIM   512   // D == U == 512

// ---------------- scratch (no allocs allowed) ----------------
// QKV: 3 * 8 * 2048 * 512 floats = 100 MB
__device__ float g_qkv[3ULL * BATCH * SEQ * DIM];
// scores: 8 * 2048 * 2048 floats = 134 MB
__device__ float g_scores[(size_t)BATCH * SEQ * SEQ];

// ---------------- SGEMM: C[M,N] = A[M,K] * op(B) (+bias) ----------------
// BT=false: B is [K,N] row-major (NN).  BT=true: B is [N,K] row-major (NT, C=A*B^T).
// Tiles: 128x128 block, BK=16, 8x8 per thread, 256 threads.
#define BM 128
#define BN 128
#define BK 16
#define TM 8
#define TN 8

template<bool BT, bool HASBIAS>
__global__ __launch_bounds__(256)
void sgemm_kernel(const float* __restrict__ Ag, const float* __restrict__ Bg,
                  const float* __restrict__ biasg, float* __restrict__ Cg,
                  int M, int N, int K,
                  size_t strideA, size_t strideB, size_t strideC)
{
    const int b = blockIdx.z;
    const float* A = Ag + (size_t)b * strideA;
    const float* B = Bg + (size_t)b * strideB;
    float*       C = Cg + (size_t)b * strideC;

    __shared__ float As[BK][BM];
    __shared__ float Bs[BK][BN];

    const int tid = threadIdx.x;
    const int tr  = tid / (BN / TN);   // 0..15
    const int tc  = tid % (BN / TN);   // 0..15

    const int m0 = blockIdx.y * BM;
    const int n0 = blockIdx.x * BN;

    float acc[TM][TN];
#pragma unroll
    for (int i = 0; i < TM; i++)
#pragma unroll
        for (int j = 0; j < TN; j++)
            acc[i][j] = 0.0f;

    for (int k0 = 0; k0 < K; k0 += BK) {
        // ---- load A tile: 128 rows x 16 k  (row-major, 4 float4 per row) ----
#pragma unroll
        for (int j = 0; j < 2; j++) {
            int i   = tid * 2 + j;           // 0..511 float4 index
            int row = i >> 2;                // 0..127
            int c4  = i & 3;                 // 0..3
            float4 v = *(const float4*)(A + (size_t)(m0 + row) * K + k0 + c4 * 4);
            As[c4 * 4 + 0][row] = v.x;
            As[c4 * 4 + 1][row] = v.y;
            As[c4 * 4 + 2][row] = v.z;
            As[c4 * 4 + 3][row] = v.w;
        }
        // ---- load B tile ----
        if (BT) {
            // B[N,K] row-major: rows n0..n0+127, cols k0..k0+15
#pragma unroll
            for (int j = 0; j < 2; j++) {
                int i   = tid * 2 + j;
                int row = i >> 2;            // n offset
                int c4  = i & 3;
                float4 v = *(const float4*)(B + (size_t)(n0 + row) * K + k0 + c4 * 4);
                Bs[c4 * 4 + 0][row] = v.x;
                Bs[c4 * 4 + 1][row] = v.y;
                Bs[c4 * 4 + 2][row] = v.z;
                Bs[c4 * 4 + 3][row] = v.w;
            }
        } else {
            // B[K,N] row-major: rows k0..k0+15, cols n0..n0+127
#pragma unroll
            for (int j = 0; j < 2; j++) {
                int i   = tid * 2 + j;       // 0..511
                int row = i >> 5;            // k offset, 32 float4 per row
                int c4  = i & 31;
                float4 v = *(const float4*)(B + (size_t)(k0 + row) * N + n0 + c4 * 4);
                *(float4*)&Bs[row][c4 * 4] = v;
            }
        }
        __syncthreads();

        // ---- compute ----
#pragma unroll
        for (int kk = 0; kk < BK; kk++) {
            float a[TM], bb[TN];
#pragma unroll
            for (int i = 0; i < TM; i += 4)
                *(float4*)&a[i] = *(const float4*)&As[kk][tr * TM + i];
#pragma unroll
            for (int i = 0; i < TN; i += 4)
                *(float4*)&bb[i] = *(const float4*)&Bs[kk][tc * TN + i];
#pragma unroll
            for (int i = 0; i < TM; i++)
#pragma unroll
                for (int j = 0; j < TN; j++)
                    acc[i][j] += a[i] * bb[j];
        }
        __syncthreads();
    }

    // ---- epilogue ----
#pragma unroll
    for (int i = 0; i < TM; i++) {
        int m = m0 + tr * TM + i;
#pragma unroll
        for (int j = 0; j < TN; j += 4) {
            int n = n0 + tc * TN + j;
            float4 v = make_float4(acc[i][j], acc[i][j + 1], acc[i][j + 2], acc[i][j + 3]);
            if (HASBIAS) {
                v.x += biasg[n + 0];
                v.y += biasg[n + 1];
                v.z += biasg[n + 2];
                v.w += biasg[n + 3];
            }
            *(float4*)(C + (size_t)m * N + n) = v;
        }
    }
}

// ---- fused QKV projection: z = 0/1/2 selects (Wq,bq,Q), (Wk,bk,K), (Wv,bv,V) ----
__global__ __launch_bounds__(256)
void qkv_proj_kernel(const float* __restrict__ X,
                     const float* __restrict__ Wq, const float* __restrict__ bq,
                     const float* __restrict__ Wk, const float* __restrict__ bk,
                     const float* __restrict__ Wv, const float* __restrict__ bv,
                     float* __restrict__ QKV)
{
    const int which = blockIdx.z;
    const float* B    = (which == 0) ? Wq : (which == 1) ? Wk : Wv;
    const float* bias = (which == 0) ? bq : (which == 1) ? bk : bv;
    float* C = QKV + (size_t)which * BATCH * SEQ * DIM;

    const int Mloc = BATCH * SEQ;     // 16384
    const int Nloc = DIM, Kloc = DIM;

    __shared__ float As[BK][BM];
    __shared__ float Bs[BK][BN];

    const int tid = threadIdx.x;
    const int tr  = tid / (BN / TN);
    const int tc  = tid % (BN / TN);
    const int m0 = blockIdx.y * BM;
    const int n0 = blockIdx.x * BN;
    (void)Mloc;

    float acc[TM][TN];
#pragma unroll
    for (int i = 0; i < TM; i++)
#pragma unroll
        for (int j = 0; j < TN; j++)
            acc[i][j] = 0.0f;

    for (int k0 = 0; k0 < Kloc; k0 += BK) {
#pragma unroll
        for (int j = 0; j < 2; j++) {
            int i   = tid * 2 + j;
            int row = i >> 2;
            int c4  = i & 3;
            float4 v = *(const float4*)(X + (size_t)(m0 + row) * Kloc + k0 + c4 * 4);
            As[c4 * 4 + 0][row] = v.x;
            As[c4 * 4 + 1][row] = v.y;
            As[c4 * 4 + 2][row] = v.z;
            As[c4 * 4 + 3][row] = v.w;
        }
#pragma unroll
        for (int j = 0; j < 2; j++) {
            int i   = tid * 2 + j;
            int row = i >> 5;
            int c4  = i & 31;
            float4 v = *(const float4*)(B + (size_t)(k0 + row) * Nloc + n0 + c4 * 4);
            *(float4*)&Bs[row][c4 * 4] = v;
        }
        __syncthreads();

#pragma unroll
        for (int kk = 0; kk < BK; kk++) {
            float a[TM], bb[TN];
#pragma unroll
            for (int i = 0; i < TM; i += 4)
                *(float4*)&a[i] = *(const float4*)&As[kk][tr * TM + i];
#pragma unroll
            for (int i = 0; i < TN; i += 4)
                *(float4*)&bb[i] = *(const float4*)&Bs[kk][tc * TN + i];
#pragma unroll
            for (int i = 0; i < TM; i++)
#pragma unroll
                for (int j = 0; j < TN; j++)
                    acc[i][j] += a[i] * bb[j];
        }
        __syncthreads();
    }

#pragma unroll
    for (int i = 0; i < TM; i++) {
        int m = m0 + tr * TM + i;
#pragma unroll
        for (int j = 0; j < TN; j += 4) {
            int n = n0 + tc * TN + j;
            float4 v = make_float4(acc[i][j] + bias[n + 0],
                                   acc[i][j + 1] + bias[n + 1],
                                   acc[i][j + 2] + bias[n + 2],
                                   acc[i][j + 3] + bias[n + 3]);
            *(float4*)(C + (size_t)m * Nloc + n) = v;
        }
    }
}

// ---------------- row softmax over 2048 cols, one block per row ----------------
__global__ __launch_bounds__(256)
void softmax_rows_kernel(float* __restrict__ S)
{
    const int NC = SEQ;                       // 2048
    size_t row = blockIdx.x;
    float4* p4 = (float4*)(S + row * (size_t)NC);
    const int t = threadIdx.x;

    float4 v0 = p4[t];
    float4 v1 = p4[t + 256];

    float lmax = fmaxf(fmaxf(fmaxf(v0.x, v0.y), fmaxf(v0.z, v0.w)),
                       fmaxf(fmaxf(v1.x, v1.y), fmaxf(v1.z, v1.w)));
#pragma unroll
    for (int o = 16; o > 0; o >>= 1)
        lmax = fmaxf(lmax, __shfl_xor_sync(0xffffffffu, lmax, o));

    __shared__ float sm_max[8];
    __shared__ float sm_sum[8];
    if ((t & 31) == 0) sm_max[t >> 5] = lmax;
    __syncthreads();
    float m = sm_max[0];
#pragma unroll
    for (int i = 1; i < 8; i++) m = fmaxf(m, sm_max[i]);

    v0.x = __expf(v0.x - m); v0.y = __expf(v0.y - m);
    v0.z = __expf(v0.z - m); v0.w = __expf(v0.w - m);
    v1.x = __expf(v1.x - m); v1.y = __expf(v1.y - m);
    v1.z = __expf(v1.z - m); v1.w = __expf(v1.w - m);

    float lsum = (v0.x + v0.y + v0.z + v0.w) + (v1.x + v1.y + v1.z + v1.w);
#pragma unroll
    for (int o = 16; o > 0; o >>= 1)
        lsum += __shfl_xor_sync(0xffffffffu, lsum, o);
    if ((t & 31) == 0) sm_sum[t >> 5] = lsum;
    __syncthreads();
    float s = 0.0f;
#pragma unroll
    for (int i = 0; i < 8; i++) s += sm_sum[i];

    float inv = 1.0f / s;
    v0.x *= inv; v0.y *= inv; v0.z *= inv; v0.w *= inv;
    v1.x *= inv; v1.y *= inv; v1.z *= inv; v1.w *= inv;

    p4[t]       = v0;
    p4[t + 256] = v1;
}

// ---------------- launcher ----------------
extern "C" void kernel_launch(void* const* d_in, const int* in_sizes, int n_in,
                              void* d_out, int out_size)
{
    const float* x  = (const float*)d_in[0];   // [8,2048,512]
    const float* Wq = (const float*)d_in[1];   // [512,512]
    const float* bq = (const float*)d_in[2];   // [512]
    const float* Wk = (const float*)d_in[3];
    const float* bk = (const float*)d_in[4];
    const float* Wv = (const float*)d_in[5];
    const float* bv = (const float*)d_in[6];
    float* out = (float*)d_out;                // [8,2048,512]

    float* qkv = nullptr;
    float* scores = nullptr;
    cudaGetSymbolAddress((void**)&qkv, g_qkv);
    cudaGetSymbolAddress((void**)&scores, g_scores);

    const size_t BNU = (size_t)BATCH * SEQ * DIM;   // per-matrix size
    float* Q = qkv;
    float* Kp = qkv + BNU;
    float* V = qkv + 2 * BNU;

    const int Mx = BATCH * SEQ;   // 16384

    // ---- QKV projections (fused, one launch): [16384,512] = X @ W + b, x3 ----
    {
        dim3 grid(DIM / BN, Mx / BM, 3);
        qkv_proj_kernel<<<grid, 256>>>(x, Wq, bq, Wk, bk, Wv, bv, qkv);
    }

    // ---- scores: per batch S[2048,2048] = Q_b @ K_b^T ----
    {
        dim3 grid(SEQ / BN, SEQ / BM, BATCH);
        sgemm_kernel<true, false><<<grid, 256>>>(
            Q, Kp, nullptr, scores,
            SEQ, SEQ, DIM,
            (size_t)SEQ * DIM, (size_t)SEQ * DIM, (size_t)SEQ * SEQ);
    }

    // ---- softmax over rows ----
    softmax_rows_kernel<<<BATCH * SEQ, 256>>>(scores);

    // ---- output: per batch O[2048,512] = P[2048,2048] @ V_b[2048,512] ----
    {
        dim3 grid(DIM / BN, SEQ / BM, BATCH);
        sgemm_kernel<false, false><<<grid, 256>>>(
            scores, V, nullptr, out,
            SEQ, DIM, SEQ,
            (size_t)SEQ * SEQ, (size_t)SEQ * DIM, (size_t)SEQ * DIM);
    }
}

// round 10
// speedup vs baseline: 2.5613x; 2.5613x over previous
#include <cuda_runtime.h>
#include <cuda_bf16.h>
#include <stdint.h>

// ---------------- problem constants ----------------
#define BATCH 8
#define SEQ   2048
#define DIM   512

// ---------------- scratch (device globals; no allocs allowed) ----------------
__device__ __align__(256) float g_scores[(size_t)BATCH * SEQ * SEQ];            // 134 MB
__device__ __align__(256) __nv_bfloat16 g_xh[(size_t)BATCH * SEQ * DIM];
__device__ __align__(256) __nv_bfloat16 g_xl[(size_t)BATCH * SEQ * DIM];
__device__ __align__(256) __nv_bfloat16 g_wth[3ULL * DIM * DIM];
__device__ __align__(256) __nv_bfloat16 g_wtl[3ULL * DIM * DIM];
__device__ __align__(256) __nv_bfloat16 g_qkvh[3ULL * BATCH * SEQ * DIM];
__device__ __align__(256) __nv_bfloat16 g_qkvl[3ULL * BATCH * SEQ * DIM];
__device__ __align__(256) __nv_bfloat16 g_vth[(size_t)BATCH * DIM * SEQ];       // V^T
__device__ __align__(256) __nv_bfloat16 g_vtl[(size_t)BATCH * DIM * SEQ];
__device__ __align__(256) __nv_bfloat16 g_ph[(size_t)BATCH * SEQ * SEQ];        // 67 MB
__device__ __align__(256) __nv_bfloat16 g_pl[(size_t)BATCH * SEQ * SEQ];

// ---------------- asm helpers (base-target safe: sm_80+) ----------------
__device__ __forceinline__ uint32_t smem_u32(const void* p) {
    uint32_t a;
    asm("{ .reg .u64 t; cvta.to.shared.u64 t, %1; cvt.u32.u64 %0, t; }" : "=r"(a) : "l"(p));
    return a;
}
#define CP16(sm, gp) \
    asm volatile("cp.async.cg.shared.global [%0], [%1], 16;" :: "r"(sm), "l"(gp))
#define CPCOMMIT() asm volatile("cp.async.commit_group;" ::: "memory")
#define CPWAIT0()  asm volatile("cp.async.wait_group 0;" ::: "memory")

__device__ __forceinline__ void ldsm_x4(uint32_t& r0, uint32_t& r1, uint32_t& r2, uint32_t& r3,
                                        uint32_t addr) {
    asm volatile("ldmatrix.sync.aligned.m8n8.x4.shared.b16 {%0,%1,%2,%3}, [%4];"
                 : "=r"(r0), "=r"(r1), "=r"(r2), "=r"(r3) : "r"(addr));
}
__device__ __forceinline__ void mma16816(float* c, const uint32_t* a, uint32_t b0, uint32_t b1) {
    asm volatile("mma.sync.aligned.m16n8k16.row.col.f32.bf16.bf16.f32 "
                 "{%0,%1,%2,%3}, {%4,%5,%6,%7}, {%8,%9}, {%0,%1,%2,%3};"
                 : "+f"(c[0]), "+f"(c[1]), "+f"(c[2]), "+f"(c[3])
                 : "r"(a[0]), "r"(a[1]), "r"(a[2]), "r"(a[3]), "r"(b0), "r"(b1));
}

__device__ __forceinline__ uint32_t pack2(float a, float b) {
    __nv_bfloat16 ha = __float2bfloat16(a), hb = __float2bfloat16(b);
    return (uint32_t)__bfloat16_as_ushort(ha) | ((uint32_t)__bfloat16_as_ushort(hb) << 16);
}

// ---------------- GEMM geometry ----------------
// CTA tile 128x128x32, 8 warps: warp grid 2(m) x 4(n), warp tile 64x32.
// smem row = 32 bf16 (64B) padded to 40 halfs (80B) -> conflict-free ldmatrix.
#define ROWH   40
#define TILEB  (128 * ROWH * 2)      // 10240 B per tile
#define STAGEB (4 * TILEB)           // Ah, Al, Bh, Bl
#define SMEMB  (2 * STAGEB)          // double-buffered: 81920 B

// loads one (hi,lo) tile pair: 128 rows x 32 halfs each, via cp.async 16B
__device__ __forceinline__ void load_tile_pair(uint32_t smH, uint32_t smL,
    const __nv_bfloat16* __restrict__ gh, const __nv_bfloat16* __restrict__ gl,
    int ldh, int tid)
{
#pragma unroll
    for (int j = 0; j < 2; j++) {
        int i   = j * 256 + tid;
        int row = i >> 2;
        int c   = i & 3;
        uint32_t so = (uint32_t)(row * 80 + c * 16);
        const char* gp = (const char*)(gh + (size_t)row * ldh) + c * 16;
        const char* gq = (const char*)(gl + (size_t)row * ldh) + c * 16;
        CP16(smH + so, gp);
        CP16(smL + so, gq);
    }
}

// OUTMODE 0: write fp32 C.  OUTMODE 1: bf16 hi/lo split + bias (z selects b0/b1/b2).
// A: [M,K] K-major bf16 hi/lo.  B: [N,K] K-major bf16 hi/lo.  C = A * B^T.
template<int OUTMODE>
__global__ __launch_bounds__(256)
void gemm_mma(const __nv_bfloat16* __restrict__ Ah_, const __nv_bfloat16* __restrict__ Al_,
              const __nv_bfloat16* __restrict__ Bh_, const __nv_bfloat16* __restrict__ Bl_,
              const float* __restrict__ b0p, const float* __restrict__ b1p,
              const float* __restrict__ b2p,
              float* __restrict__ C_, __nv_bfloat16* __restrict__ Oh_,
              __nv_bfloat16* __restrict__ Ol_,
              int M, int N, int K, size_t sA, size_t sB, size_t sC)
{
    extern __shared__ char smem[];
    const uint32_t sb = smem_u32(smem);
    const int tid = threadIdx.x, wid = tid >> 5, lane = tid & 31;
    const int z = blockIdx.z;

    const __nv_bfloat16* Ah = Ah_ + (size_t)z * sA;
    const __nv_bfloat16* Al = Al_ + (size_t)z * sA;
    const __nv_bfloat16* Bh = Bh_ + (size_t)z * sB;
    const __nv_bfloat16* Bl = Bl_ + (size_t)z * sB;

    const int m0 = blockIdx.y * 128;
    const int n0 = blockIdx.x * 128;
    const int wm = wid >> 2;      // 0..1
    const int wn = wid & 3;       // 0..3

    float acc[4][4][4];
#pragma unroll
    for (int a = 0; a < 4; a++)
#pragma unroll
        for (int b = 0; b < 4; b++)
#pragma unroll
            for (int c = 0; c < 4; c++) acc[a][b][c] = 0.0f;

    // ldmatrix lane decode
    const int blk = lane >> 3, r8 = lane & 7;
    const int arow = (blk & 1) * 8 + r8, ach = blk >> 1;   // A: r0/r1=rows, r2/r3=+8 cols
    const int brow = (blk >> 1) * 8 + r8, bch = blk & 1;   // B: r0/r1=k0/k8 of n0-7, r2/r3 of n8-15

    // prefetch stage 0
    load_tile_pair(sb, sb + TILEB, Ah + (size_t)m0 * K, Al + (size_t)m0 * K, K, tid);
    load_tile_pair(sb + 2 * TILEB, sb + 3 * TILEB, Bh + (size_t)n0 * K, Bl + (size_t)n0 * K, K, tid);
    CPCOMMIT();

    const int niter = K / 32;
    for (int it = 0; it < niter; it++) {
        CPWAIT0();
        __syncthreads();

        if (it + 1 < niter) {
            const uint32_t nb = sb + ((it + 1) & 1) * STAGEB;
            const int k0 = (it + 1) * 32;
            load_tile_pair(nb, nb + TILEB,
                           Ah + (size_t)m0 * K + k0, Al + (size_t)m0 * K + k0, K, tid);
            load_tile_pair(nb + 2 * TILEB, nb + 3 * TILEB,
                           Bh + (size_t)n0 * K + k0, Bl + (size_t)n0 * K + k0, K, tid);
            CPCOMMIT();
        }

        const uint32_t base = sb + (it & 1) * STAGEB;
        const uint32_t aH = base, aL = base + TILEB, bH = base + 2 * TILEB, bL = base + 3 * TILEB;

#pragma unroll
        for (int ks = 0; ks < 2; ks++) {
            uint32_t ahf[4][4], alf[4][4], bhf[2][4], blf[2][4];
#pragma unroll
            for (int mi = 0; mi < 4; mi++) {
                uint32_t off = (uint32_t)((wm * 64 + mi * 16 + arow) * 80 + (ks * 2 + ach) * 16);
                ldsm_x4(ahf[mi][0], ahf[mi][1], ahf[mi][2], ahf[mi][3], aH + off);
                ldsm_x4(alf[mi][0], alf[mi][1], alf[mi][2], alf[mi][3], aL + off);
            }
#pragma unroll
            for (int n2 = 0; n2 < 2; n2++) {
                uint32_t off = (uint32_t)((wn * 32 + n2 * 16 + brow) * 80 + (ks * 2 + bch) * 16);
                ldsm_x4(bhf[n2][0], bhf[n2][1], bhf[n2][2], bhf[n2][3], bH + off);
                ldsm_x4(blf[n2][0], blf[n2][1], blf[n2][2], blf[n2][3], bL + off);
            }
#pragma unroll
            for (int mi = 0; mi < 4; mi++)
#pragma unroll
                for (int ni = 0; ni < 4; ni++) {
                    const int n2 = ni >> 1, p = (ni & 1) * 2;
                    mma16816(acc[mi][ni], ahf[mi], bhf[n2][p], bhf[n2][p + 1]);
                    mma16816(acc[mi][ni], ahf[mi], blf[n2][p], blf[n2][p + 1]);
                    mma16816(acc[mi][ni], alf[mi], bhf[n2][p], bhf[n2][p + 1]);
                }
        }
        __syncthreads();
    }

    // ---- epilogue ----
    const int g  = lane >> 2;
    const int c2 = (lane & 3) * 2;
#pragma unroll
    for (int mi = 0; mi < 4; mi++) {
        const int r1 = m0 + wm * 64 + mi * 16 + g;
        const int r2 = r1 + 8;
#pragma unroll
        for (int ni = 0; ni < 4; ni++) {
            const int col = n0 + wn * 32 + ni * 8 + c2;
            if (OUTMODE == 0) {
                float* C = C_ + (size_t)z * sC;
                *(float2*)(C + (size_t)r1 * N + col) = make_float2(acc[mi][ni][0], acc[mi][ni][1]);
                *(float2*)(C + (size_t)r2 * N + col) = make_float2(acc[mi][ni][2], acc[mi][ni][3]);
            } else {
                const float* bias = (z == 0) ? b0p : (z == 1) ? b1p : b2p;
                float v0 = acc[mi][ni][0] + bias[col];
                float v1 = acc[mi][ni][1] + bias[col + 1];
                float v2 = acc[mi][ni][2] + bias[col];
                float v3 = acc[mi][ni][3] + bias[col + 1];
                float h0 = __bfloat162float(__float2bfloat16(v0));
                float h1 = __bfloat162float(__float2bfloat16(v1));
                float h2 = __bfloat162float(__float2bfloat16(v2));
                float h3 = __bfloat162float(__float2bfloat16(v3));
                __nv_bfloat16* Oh = Oh_ + (size_t)z * sC;
                __nv_bfloat16* Ol = Ol_ + (size_t)z * sC;
                *(uint32_t*)(Oh + (size_t)r1 * N + col) = pack2(h0, h1);
                *(uint32_t*)(Oh + (size_t)r2 * N + col) = pack2(h2, h3);
                *(uint32_t*)(Ol + (size_t)r1 * N + col) = pack2(v0 - h0, v1 - h1);
                *(uint32_t*)(Ol + (size_t)r2 * N + col) = pack2(v2 - h2, v3 - h3);
            }
        }
    }
}

// ---------------- prep: split X into bf16 hi/lo ----------------
__global__ __launch_bounds__(256)
void split_x_kernel(const float* __restrict__ x, __nv_bfloat16* __restrict__ h,
                    __nv_bfloat16* __restrict__ l)
{
    size_t i = (size_t)blockIdx.x * 256 + threadIdx.x;
    float4 v = ((const float4*)x)[i];
    float vv[4] = {v.x, v.y, v.z, v.w};
    float hi[4], lo[4];
#pragma unroll
    for (int t = 0; t < 4; t++) {
        __nv_bfloat16 hb = __float2bfloat16(vv[t]);
        hi[t] = __bfloat162float(hb);
        lo[t] = vv[t] - hi[t];
    }
    ((uint2*)h)[i] = make_uint2(pack2(hi[0], hi[1]), pack2(hi[2], hi[3]));
    ((uint2*)l)[i] = make_uint2(pack2(lo[0], lo[1]), pack2(lo[2], lo[3]));
}

// ---------------- prep: transpose + split W (512x512) x3 ----------------
__global__ __launch_bounds__(256)
void wtrans_kernel(const float* __restrict__ Wq, const float* __restrict__ Wk,
                   const float* __restrict__ Wv,
                   __nv_bfloat16* __restrict__ th, __nv_bfloat16* __restrict__ tl)
{
    __shared__ float t[32][33];
    const int z = blockIdx.z;
    const float* W = (z == 0) ? Wq : (z == 1) ? Wk : Wv;
    const int u0 = blockIdx.x * 32, d0 = blockIdx.y * 32;
    const int tx = threadIdx.x & 31, ty = threadIdx.x >> 5;
#pragma unroll
    for (int k = 0; k < 32; k += 8)
        t[ty + k][tx] = W[(size_t)(d0 + ty + k) * DIM + u0 + tx];
    __syncthreads();
    __nv_bfloat16* oh = th + (size_t)z * DIM * DIM;
    __nv_bfloat16* ol = tl + (size_t)z * DIM * DIM;
#pragma unroll
    for (int k = 0; k < 32; k += 8) {
        float v = t[tx][ty + k];
        __nv_bfloat16 hb = __float2bfloat16(v);
        float lo = v - __bfloat162float(hb);
        oh[(size_t)(u0 + ty + k) * DIM + d0 + tx] = hb;
        ol[(size_t)(u0 + ty + k) * DIM + d0 + tx] = __float2bfloat16(lo);
    }
}

// ---------------- prep: transpose V (per batch [S][D] -> [D][S]) hi/lo ----------------
__global__ __launch_bounds__(256)
void vtrans_kernel(const __nv_bfloat16* __restrict__ vh, const __nv_bfloat16* __restrict__ vl,
                   __nv_bfloat16* __restrict__ oth, __nv_bfloat16* __restrict__ otl)
{
    __shared__ __nv_bfloat16 th[32][33];
    __shared__ __nv_bfloat16 tl2[32][33];
    const int b = blockIdx.z;
    const int s0 = blockIdx.x * 32, d0 = blockIdx.y * 32;
    const __nv_bfloat16* ih = vh + (size_t)b * SEQ * DIM;
    const __nv_bfloat16* il = vl + (size_t)b * SEQ * DIM;
    const int tx = threadIdx.x & 31, ty = threadIdx.x >> 5;
#pragma unroll
    for (int k = 0; k < 32; k += 8) {
        th[ty + k][tx]  = ih[(size_t)(s0 + ty + k) * DIM + d0 + tx];
        tl2[ty + k][tx] = il[(size_t)(s0 + ty + k) * DIM + d0 + tx];
    }
    __syncthreads();
    __nv_bfloat16* oh = oth + (size_t)b * DIM * SEQ;
    __nv_bfloat16* ol = otl + (size_t)b * DIM * SEQ;
#pragma unroll
    for (int k = 0; k < 32; k += 8) {
        oh[(size_t)(d0 + ty + k) * SEQ + s0 + tx] = th[tx][ty + k];
        ol[(size_t)(d0 + ty + k) * SEQ + s0 + tx] = tl2[tx][ty + k];
    }
}

// ---------------- softmax: fp32 scores -> bf16 hi/lo P ----------------
__global__ __launch_bounds__(256)
void softmax_rows_kernel(const float* __restrict__ S, __nv_bfloat16* __restrict__ Ph,
                         __nv_bfloat16* __restrict__ Pl)
{
    size_t row = blockIdx.x;
    const float4* p4 = (const float4*)(S + row * (size_t)SEQ);
    const int t = threadIdx.x;

    float4 v0 = p4[t];
    float4 v1 = p4[t + 256];

    float lmax = fmaxf(fmaxf(fmaxf(v0.x, v0.y), fmaxf(v0.z, v0.w)),
                       fmaxf(fmaxf(v1.x, v1.y), fmaxf(v1.z, v1.w)));
#pragma unroll
    for (int o = 16; o > 0; o >>= 1)
        lmax = fmaxf(lmax, __shfl_xor_sync(0xffffffffu, lmax, o));

    __shared__ float sm_max[8];
    __shared__ float sm_sum[8];
    if ((t & 31) == 0) sm_max[t >> 5] = lmax;
    __syncthreads();
    float m = sm_max[0];
#pragma unroll
    for (int i = 1; i < 8; i++) m = fmaxf(m, sm_max[i]);

    v0.x = __expf(v0.x - m); v0.y = __expf(v0.y - m);
    v0.z = __expf(v0.z - m); v0.w = __expf(v0.w - m);
    v1.x = __expf(v1.x - m); v1.y = __expf(v1.y - m);
    v1.z = __expf(v1.z - m); v1.w = __expf(v1.w - m);

    float lsum = (v0.x + v0.y + v0.z + v0.w) + (v1.x + v1.y + v1.z + v1.w);
#pragma unroll
    for (int o = 16; o > 0; o >>= 1)
        lsum += __shfl_xor_sync(0xffffffffu, lsum, o);
    if ((t & 31) == 0) sm_sum[t >> 5] = lsum;
    __syncthreads();
    float s = 0.0f;
#pragma unroll
    for (int i = 0; i < 8; i++) s += sm_sum[i];

    float inv = 1.0f / s;
    float a[8] = {v0.x * inv, v0.y * inv, v0.z * inv, v0.w * inv,
                  v1.x * inv, v1.y * inv, v1.z * inv, v1.w * inv};
    float hi[8], lo[8];
#pragma unroll
    for (int i = 0; i < 8; i++) {
        __nv_bfloat16 hb = __float2bfloat16(a[i]);
        hi[i] = __bfloat162float(hb);
        lo[i] = a[i] - hi[i];
    }
    uint2* oh = (uint2*)(Ph + row * (size_t)SEQ);
    uint2* ol = (uint2*)(Pl + row * (size_t)SEQ);
    oh[t]       = make_uint2(pack2(hi[0], hi[1]), pack2(hi[2], hi[3]));
    oh[t + 256] = make_uint2(pack2(hi[4], hi[5]), pack2(hi[6], hi[7]));
    ol[t]       = make_uint2(pack2(lo[0], lo[1]), pack2(lo[2], lo[3]));
    ol[t + 256] = make_uint2(pack2(lo[4], lo[5]), pack2(lo[6], lo[7]));
}

// ---------------- launcher ----------------
extern "C" void kernel_launch(void* const* d_in, const int* in_sizes, int n_in,
                              void* d_out, int out_size)
{
    const float* x  = (const float*)d_in[0];
    const float* Wq = (const float*)d_in[1];
    const float* bq = (const float*)d_in[2];
    const float* Wk = (const float*)d_in[3];
    const float* bk = (const float*)d_in[4];
    const float* Wv = (const float*)d_in[5];
    const float* bv = (const float*)d_in[6];
    float* out = (float*)d_out;

    float* scores = nullptr;
    __nv_bfloat16 *xh, *xl, *wth, *wtl, *qkvh, *qkvl, *vth, *vtl, *ph, *pl;
    cudaGetSymbolAddress((void**)&scores, g_scores);
    cudaGetSymbolAddress((void**)&xh, g_xh);
    cudaGetSymbolAddress((void**)&xl, g_xl);
    cudaGetSymbolAddress((void**)&wth, g_wth);
    cudaGetSymbolAddress((void**)&wtl, g_wtl);
    cudaGetSymbolAddress((void**)&qkvh, g_qkvh);
    cudaGetSymbolAddress((void**)&qkvl, g_qkvl);
    cudaGetSymbolAddress((void**)&vth, g_vth);
    cudaGetSymbolAddress((void**)&vtl, g_vtl);
    cudaGetSymbolAddress((void**)&ph, g_ph);
    cudaGetSymbolAddress((void**)&pl, g_pl);

    cudaFuncSetAttribute(gemm_mma<0>, cudaFuncAttributeMaxDynamicSharedMemorySize, SMEMB);
    cudaFuncSetAttribute(gemm_mma<1>, cudaFuncAttributeMaxDynamicSharedMemorySize, SMEMB);

    const int    Mx = BATCH * SEQ;                 // 16384
    const size_t MS = (size_t)BATCH * SEQ * DIM;   // per-matrix split size

    // prep: split X, transpose+split W
    split_x_kernel<<<(Mx * DIM) / 4 / 256, 256>>>(x, xh, xl);
    {
        dim3 g(DIM / 32, DIM / 32, 3);
        wtrans_kernel<<<g, 256>>>(Wq, Wk, Wv, wth, wtl);
    }

    // QKV projections: [16384,512] x3; A = X (stride 0), B = W^T; out split + bias
    {
        dim3 g(DIM / 128, Mx / 128, 3);
        gemm_mma<1><<<g, 256, SMEMB>>>(
            xh, xl, wth, wtl, bq, bk, bv,
            nullptr, qkvh, qkvl,
            Mx, DIM, DIM, 0, (size_t)DIM * DIM, MS);
    }

    // transpose V -> [D][S] per batch
    {
        dim3 g(SEQ / 32, DIM / 32, BATCH);
        vtrans_kernel<<<g, 256>>>(qkvh + 2 * MS, qkvl + 2 * MS, vth, vtl);
    }

    // scores: per batch S = Q @ K^T
    {
        dim3 g(SEQ / 128, SEQ / 128, BATCH);
        gemm_mma<0><<<g, 256, SMEMB>>>(
            qkvh, qkvl, qkvh + MS, qkvl + MS, nullptr, nullptr, nullptr,
            scores, nullptr, nullptr,
            SEQ, SEQ, DIM, (size_t)SEQ * DIM, (size_t)SEQ * DIM, (size_t)SEQ * SEQ);
    }

    // softmax -> split P
    softmax_rows_kernel<<<BATCH * SEQ, 256>>>(scores, ph, pl);

    // out: per batch O = P @ V   (B = V^T, [N=512][K=2048])
    {
        dim3 g(DIM / 128, SEQ / 128, BATCH);
        gemm_mma<0><<<g, 256, SMEMB>>>(
            ph, pl, vth, vtl, nullptr, nullptr, nullptr,
            out, nullptr, nullptr,
            SEQ, DIM, SEQ, (size_t)SEQ * SEQ, (size_t)DIM * SEQ, (size_t)SEQ * DIM);
    }
}

// round 13
// speedup vs baseline: 2.9256x; 1.1422x over previous
#include <cuda_runtime.h>
#include <cuda_fp16.h>
#include <stdint.h>

// ---------------- problem constants ----------------
#define BATCH 8
#define SEQ   2048
#define DIM   512

// ---------------- scratch (device globals; no allocs allowed) ----------------
__device__ __align__(256) float g_scores[(size_t)BATCH * SEQ * SEQ];            // 134 MB
__device__ __align__(256) __half g_xh[(size_t)BATCH * SEQ * DIM];
__device__ __align__(256) __half g_xl[(size_t)BATCH * SEQ * DIM];
__device__ __align__(256) __half g_wth[3ULL * DIM * DIM];                       // (W*256)^T split
__device__ __align__(256) __half g_wtl[3ULL * DIM * DIM];
__device__ __align__(256) __half g_qkvh[3ULL * BATCH * SEQ * DIM];
__device__ __align__(256) __half g_qkvl[3ULL * BATCH * SEQ * DIM];
__device__ __align__(256) __half g_vth[(size_t)BATCH * DIM * SEQ];              // V^T
__device__ __align__(256) __half g_vtl[(size_t)BATCH * DIM * SEQ];
__device__ __align__(256) __half g_ph[(size_t)BATCH * SEQ * SEQ];               // P (hi only), 67 MB

// ---------------- asm helpers (base-target safe: sm_80+) ----------------
__device__ __forceinline__ uint32_t smem_u32(const void* p) {
    uint32_t a;
    asm("{ .reg .u64 t; cvta.to.shared.u64 t, %1; cvt.u32.u64 %0, t; }" : "=r"(a) : "l"(p));
    return a;
}
#define CP16(sm, gp) \
    asm volatile("cp.async.cg.shared.global [%0], [%1], 16;" :: "r"(sm), "l"(gp))
#define CPCOMMIT() asm volatile("cp.async.commit_group;" ::: "memory")
#define CPWAIT0()  asm volatile("cp.async.wait_group 0;" ::: "memory")

__device__ __forceinline__ void ldsm_x4(uint32_t& r0, uint32_t& r1, uint32_t& r2, uint32_t& r3,
                                        uint32_t addr) {
    asm volatile("ldmatrix.sync.aligned.m8n8.x4.shared.b16 {%0,%1,%2,%3}, [%4];"
                 : "=r"(r0), "=r"(r1), "=r"(r2), "=r"(r3) : "r"(addr));
}
__device__ __forceinline__ void mma16816(float* c, const uint32_t* a, uint32_t b0, uint32_t b1) {
    asm volatile("mma.sync.aligned.m16n8k16.row.col.f32.f16.f16.f32 "
                 "{%0,%1,%2,%3}, {%4,%5,%6,%7}, {%8,%9}, {%0,%1,%2,%3};"
                 : "+f"(c[0]), "+f"(c[1]), "+f"(c[2]), "+f"(c[3])
                 : "r"(a[0]), "r"(a[1]), "r"(a[2]), "r"(a[3]), "r"(b0), "r"(b1));
}

__device__ __forceinline__ uint32_t pack2h(float a, float b) {
    __half2 h = __floats2half2_rn(a, b);
    return *(uint32_t*)&h;
}

// ---------------- GEMM geometry ----------------
// CTA tile 128x128x32, 8 warps: warp grid 2(m) x 4(n), warp tile 64x32.
// smem row = 32 halfs (64B) padded to 40 halfs (80B) -> conflict-free ldmatrix.
#define ROWH   40
#define TILEB  (128 * ROWH * 2)      // 10240 B per tile
#define STAGEB (4 * TILEB)           // Ah, Al, Bh, Bl
#define SMEMB  (2 * STAGEB)          // double-buffered: 81920 B

// one 128x32 half tile via cp.async 16B
__device__ __forceinline__ void load_tile(uint32_t sm,
    const __half* __restrict__ g, int ld, int tid)
{
#pragma unroll
    for (int j = 0; j < 2; j++) {
        int i   = j * 256 + tid;
        int row = i >> 2;
        int c   = i & 3;
        CP16(sm + (uint32_t)(row * 80 + c * 16),
             (const char*)(g + (size_t)row * ld) + c * 16);
    }
}

// OUTMODE 0: write fp32 C.  OUTMODE 1: scale 1/256 + bias, write half hi/lo split.
// ALO 1: 3-term (A hi/lo).  ALO 0: 2-term (A hi only; Al_ ignored).
// A: [M,K] K-major half.  B: [N,K] K-major half hi/lo.  C = A * B^T.
template<int OUTMODE, int ALO>
__global__ __launch_bounds__(256, 2)
void gemm_mma(const __half* __restrict__ Ah_, const __half* __restrict__ Al_,
              const __half* __restrict__ Bh_, const __half* __restrict__ Bl_,
              const float* __restrict__ b0p, const float* __restrict__ b1p,
              const float* __restrict__ b2p,
              float* __restrict__ C_, __half* __restrict__ Oh_,
              __half* __restrict__ Ol_,
              int M, int N, int K, size_t sA, size_t sB, size_t sC)
{
    extern __shared__ char smem[];
    const uint32_t sb = smem_u32(smem);
    const int tid = threadIdx.x, wid = tid >> 5, lane = tid & 31;
    const int z = blockIdx.z;

    const __half* Ah = Ah_ + (size_t)z * sA;
    const __half* Al = ALO ? (Al_ + (size_t)z * sA) : nullptr;
    const __half* Bh = Bh_ + (size_t)z * sB;
    const __half* Bl = Bl_ + (size_t)z * sB;

    const int m0 = blockIdx.y * 128;
    const int n0 = blockIdx.x * 128;
    const int wm = wid >> 2;      // 0..1
    const int wn = wid & 3;       // 0..3

    float acc[4][4][4];
#pragma unroll
    for (int a = 0; a < 4; a++)
#pragma unroll
        for (int b = 0; b < 4; b++)
#pragma unroll
            for (int c = 0; c < 4; c++) acc[a][b][c] = 0.0f;

    // ldmatrix lane decode
    const int blk = lane >> 3, r8 = lane & 7;
    const int arow = (blk & 1) * 8 + r8, ach = blk >> 1;
    const int brow = (blk >> 1) * 8 + r8, bch = blk & 1;

    // prefetch stage 0
    load_tile(sb, Ah + (size_t)m0 * K, K, tid);
    if (ALO) load_tile(sb + TILEB, Al + (size_t)m0 * K, K, tid);
    load_tile(sb + 2 * TILEB, Bh + (size_t)n0 * K, K, tid);
    load_tile(sb + 3 * TILEB, Bl + (size_t)n0 * K, K, tid);
    CPCOMMIT();

    const int niter = K / 32;
    for (int it = 0; it < niter; it++) {
        CPWAIT0();
        __syncthreads();

        if (it + 1 < niter) {
            const uint32_t nb = sb + ((it + 1) & 1) * STAGEB;
            const int k0 = (it + 1) * 32;
            load_tile(nb, Ah + (size_t)m0 * K + k0, K, tid);
            if (ALO) load_tile(nb + TILEB, Al + (size_t)m0 * K + k0, K, tid);
            load_tile(nb + 2 * TILEB, Bh + (size_t)n0 * K + k0, K, tid);
            load_tile(nb + 3 * TILEB, Bl + (size_t)n0 * K + k0, K, tid);
            CPCOMMIT();
        }

        const uint32_t base = sb + (it & 1) * STAGEB;
        const uint32_t aH = base, aL = base + TILEB, bH = base + 2 * TILEB, bL = base + 3 * TILEB;

#pragma unroll
        for (int ks = 0; ks < 2; ks++) {
            uint32_t ahf[4][4], alf[4][4], bhf[2][4], blf[2][4];
#pragma unroll
            for (int mi = 0; mi < 4; mi++) {
                uint32_t off = (uint32_t)((wm * 64 + mi * 16 + arow) * 80 + (ks * 2 + ach) * 16);
                ldsm_x4(ahf[mi][0], ahf[mi][1], ahf[mi][2], ahf[mi][3], aH + off);
                if (ALO) ldsm_x4(alf[mi][0], alf[mi][1], alf[mi][2], alf[mi][3], aL + off);
            }
#pragma unroll
            for (int n2 = 0; n2 < 2; n2++) {
                uint32_t off = (uint32_t)((wn * 32 + n2 * 16 + brow) * 80 + (ks * 2 + bch) * 16);
                ldsm_x4(bhf[n2][0], bhf[n2][1], bhf[n2][2], bhf[n2][3], bH + off);
                ldsm_x4(blf[n2][0], blf[n2][1], blf[n2][2], blf[n2][3], bL + off);
            }
#pragma unroll
            for (int mi = 0; mi < 4; mi++)
#pragma unroll
                for (int ni = 0; ni < 4; ni++) {
                    const int n2 = ni >> 1, p = (ni & 1) * 2;
                    mma16816(acc[mi][ni], ahf[mi], bhf[n2][p], bhf[n2][p + 1]);
                    mma16816(acc[mi][ni], ahf[mi], blf[n2][p], blf[n2][p + 1]);
                    if (ALO) mma16816(acc[mi][ni], alf[mi], bhf[n2][p], bhf[n2][p + 1]);
                }
        }
    }

    // ---- epilogue ----
    const int g  = lane >> 2;
    const int c2 = (lane & 3) * 2;
#pragma unroll
    for (int mi = 0; mi < 4; mi++) {
        const int r1 = m0 + wm * 64 + mi * 16 + g;
        const int r2 = r1 + 8;
#pragma unroll
        for (int ni = 0; ni < 4; ni++) {
            const int col = n0 + wn * 32 + ni * 8 + c2;
            if (OUTMODE == 0) {
                float* C = C_ + (size_t)z * sC;
                *(float2*)(C + (size_t)r1 * N + col) = make_float2(acc[mi][ni][0], acc[mi][ni][1]);
                *(float2*)(C + (size_t)r2 * N + col) = make_float2(acc[mi][ni][2], acc[mi][ni][3]);
            } else {
                const float* bias = (z == 0) ? b0p : (z == 1) ? b1p : b2p;
                const float s = 0.00390625f;   // 1/256 compensates W*256 pre-scale
                float v0 = acc[mi][ni][0] * s + bias[col];
                float v1 = acc[mi][ni][1] * s + bias[col + 1];
                float v2 = acc[mi][ni][2] * s + bias[col];
                float v3 = acc[mi][ni][3] * s + bias[col + 1];
                float h0 = __half2float(__float2half_rn(v0));
                float h1 = __half2float(__float2half_rn(v1));
                float h2 = __half2float(__float2half_rn(v2));
                float h3 = __half2float(__float2half_rn(v3));
                __half* Oh = Oh_ + (size_t)z * sC;
                __half* Ol = Ol_ + (size_t)z * sC;
                *(uint32_t*)(Oh + (size_t)r1 * N + col) = pack2h(h0, h1);
                *(uint32_t*)(Oh + (size_t)r2 * N + col) = pack2h(h2, h3);
                *(uint32_t*)(Ol + (size_t)r1 * N + col) = pack2h(v0 - h0, v1 - h1);
                *(uint32_t*)(Ol + (size_t)r2 * N + col) = pack2h(v2 - h2, v3 - h3);
            }
        }
    }
}

// ---------------- prep: split X into fp16 hi/lo ----------------
__global__ __launch_bounds__(256)
void split_x_kernel(const float* __restrict__ x, __half* __restrict__ h,
                    __half* __restrict__ l)
{
    size_t i = (size_t)blockIdx.x * 256 + threadIdx.x;
    float4 v = ((const float4*)x)[i];
    float vv[4] = {v.x, v.y, v.z, v.w};
    float hi[4], lo[4];
#pragma unroll
    for (int t = 0; t < 4; t++) {
        __half hb = __float2half_rn(vv[t]);
        hi[t] = __half2float(hb);
        lo[t] = vv[t] - hi[t];
    }
    ((uint2*)h)[i] = make_uint2(pack2h(hi[0], hi[1]), pack2h(hi[2], hi[3]));
    ((uint2*)l)[i] = make_uint2(pack2h(lo[0], lo[1]), pack2h(lo[2], lo[3]));
}

// ---------------- prep: transpose + split (W*256) x3 ----------------
__global__ __launch_bounds__(256)
void wtrans_kernel(const float* __restrict__ Wq, const float* __restrict__ Wk,
                   const float* __restrict__ Wv,
                   __half* __restrict__ th, __half* __restrict__ tl)
{
    __shared__ float t[32][33];
    const int z = blockIdx.z;
    const float* W = (z == 0) ? Wq : (z == 1) ? Wk : Wv;
    const int u0 = blockIdx.x * 32, d0 = blockIdx.y * 32;
    const int tx = threadIdx.x & 31, ty = threadIdx.x >> 5;
#pragma unroll
    for (int k = 0; k < 32; k += 8)
        t[ty + k][tx] = W[(size_t)(d0 + ty + k) * DIM + u0 + tx];
    __syncthreads();
    __half* oh = th + (size_t)z * DIM * DIM;
    __half* ol = tl + (size_t)z * DIM * DIM;
#pragma unroll
    for (int k = 0; k < 32; k += 8) {
        float v = t[tx][ty + k] * 256.0f;      // pre-scale: keeps lo-limb normal fp16
        __half hb = __float2half_rn(v);
        float lo = v - __half2float(hb);
        oh[(size_t)(u0 + ty + k) * DIM + d0 + tx] = hb;
        ol[(size_t)(u0 + ty + k) * DIM + d0 + tx] = __float2half_rn(lo);
    }
}

// ---------------- prep: transpose V (per batch [S][D] -> [D][S]) hi/lo ----------------
__global__ __launch_bounds__(256)
void vtrans_kernel(const __half* __restrict__ vh, const __half* __restrict__ vl,
                   __half* __restrict__ oth, __half* __restrict__ otl)
{
    __shared__ __half th[32][33];
    __shared__ __half tl2[32][33];
    const int b = blockIdx.z;
    const int s0 = blockIdx.x * 32, d0 = blockIdx.y * 32;
    const __half* ih = vh + (size_t)b * SEQ * DIM;
    const __half* il = vl + (size_t)b * SEQ * DIM;
    const int tx = threadIdx.x & 31, ty = threadIdx.x >> 5;
#pragma unroll
    for (int k = 0; k < 32; k += 8) {
        th[ty + k][tx]  = ih[(size_t)(s0 + ty + k) * DIM + d0 + tx];
        tl2[ty + k][tx] = il[(size_t)(s0 + ty + k) * DIM + d0 + tx];
    }
    __syncthreads();
    __half* oh = oth + (size_t)b * DIM * SEQ;
    __half* ol = otl + (size_t)b * DIM * SEQ;
#pragma unroll
    for (int k = 0; k < 32; k += 8) {
        oh[(size_t)(d0 + ty + k) * SEQ + s0 + tx] = th[tx][ty + k];
        ol[(size_t)(d0 + ty + k) * SEQ + s0 + tx] = tl2[tx][ty + k];
    }
}

// ---------------- softmax: fp32 scores -> fp16 P (hi only) ----------------
__global__ __launch_bounds__(256)
void softmax_rows_kernel(const float* __restrict__ S, __half* __restrict__ Ph)
{
    size_t row = blockIdx.x;
    const float4* p4 = (const float4*)(S + row * (size_t)SEQ);
    const int t = threadIdx.x;

    float4 v0 = p4[t];
    float4 v1 = p4[t + 256];

    float lmax = fmaxf(fmaxf(fmaxf(v0.x, v0.y), fmaxf(v0.z, v0.w)),
                       fmaxf(fmaxf(v1.x, v1.y), fmaxf(v1.z, v1.w)));
#pragma unroll
    for (int o = 16; o > 0; o >>= 1)
        lmax = fmaxf(lmax, __shfl_xor_sync(0xffffffffu, lmax, o));

    __shared__ float sm_max[8];
    __shared__ float sm_sum[8];
    if ((t & 31) == 0) sm_max[t >> 5] = lmax;
    __syncthreads();
    float m = sm_max[0];
#pragma unroll
    for (int i = 1; i < 8; i++) m = fmaxf(m, sm_max[i]);

    v0.x = __expf(v0.x - m); v0.y = __expf(v0.y - m);
    v0.z = __expf(v0.z - m); v0.w = __expf(v0.w - m);
    v1.x = __expf(v1.x - m); v1.y = __expf(v1.y - m);
    v1.z = __expf(v1.z - m); v1.w = __expf(v1.w - m);

    float lsum = (v0.x + v0.y + v0.z + v0.w) + (v1.x + v1.y + v1.z + v1.w);
#pragma unroll
    for (int o = 16; o > 0; o >>= 1)
        lsum += __shfl_xor_sync(0xffffffffu, lsum, o);
    if ((t & 31) == 0) sm_sum[t >> 5] = lsum;
    __syncthreads();
    float s = 0.0f;
#pragma unroll
    for (int i = 0; i < 8; i++) s += sm_sum[i];

    float inv = 1.0f / s;
    uint2* oh = (uint2*)(Ph + row * (size_t)SEQ);
    oh[t]       = make_uint2(pack2h(v0.x * inv, v0.y * inv), pack2h(v0.z * inv, v0.w * inv));
    oh[t + 256] = make_uint2(pack2h(v1.x * inv, v1.y * inv), pack2h(v1.z * inv, v1.w * inv));
}

// ---------------- launcher ----------------
extern "C" void kernel_launch(void* const* d_in, const int* in_sizes, int n_in,
                              void* d_out, int out_size)
{
    const float* x  = (const float*)d_in[0];
    const float* Wq = (const float*)d_in[1];
    const float* bq = (const float*)d_in[2];
    const float* Wk = (const float*)d_in[3];
    const float* bk = (const float*)d_in[4];
    const float* Wv = (const float*)d_in[5];
    const float* bv = (const float*)d_in[6];
    float* out = (float*)d_out;

    float* scores = nullptr;
    __half *xh, *xl, *wth, *wtl, *qkvh, *qkvl, *vth, *vtl, *ph;
    cudaGetSymbolAddress((void**)&scores, g_scores);
    cudaGetSymbolAddress((void**)&xh, g_xh);
    cudaGetSymbolAddress((void**)&xl, g_xl);
    cudaGetSymbolAddress((void**)&wth, g_wth);
    cudaGetSymbolAddress((void**)&wtl, g_wtl);
    cudaGetSymbolAddress((void**)&qkvh, g_qkvh);
    cudaGetSymbolAddress((void**)&qkvl, g_qkvl);
    cudaGetSymbolAddress((void**)&vth, g_vth);
    cudaGetSymbolAddress((void**)&vtl, g_vtl);
    cudaGetSymbolAddress((void**)&ph, g_ph);

    cudaFuncSetAttribute(gemm_mma<0, 1>, cudaFuncAttributeMaxDynamicSharedMemorySize, SMEMB);
    cudaFuncSetAttribute(gemm_mma<1, 1>, cudaFuncAttributeMaxDynamicSharedMemorySize, SMEMB);
    cudaFuncSetAttribute(gemm_mma<0, 0>, cudaFuncAttributeMaxDynamicSharedMemorySize, SMEMB);

    const int    Mx = BATCH * SEQ;                 // 16384
    const size_t MS = (size_t)BATCH * SEQ * DIM;   // per-matrix split size

    // (0) split X, (1) transpose+split W*256
    split_x_kernel<<<(Mx * DIM) / 4 / 256, 256>>>(x, xh, xl);
    {
        dim3 g(DIM / 32, DIM / 32, 3);
        wtrans_kernel<<<g, 256>>>(Wq, Wk, Wv, wth, wtl);
    }

    // (2) QKV projections: A = X (stride 0), B = (W*256)^T; out split + bias, 3-term
    {
        dim3 g(DIM / 128, Mx / 128, 3);
        gemm_mma<1, 1><<<g, 256, SMEMB>>>(
            xh, xl, wth, wtl, bq, bk, bv,
            nullptr, qkvh, qkvl,
            Mx, DIM, DIM, 0, (size_t)DIM * DIM, MS);
    }

    // (3) scores: per batch S = Q @ K^T, 3-term   <-- ncu lands here (launch index 3)
    {
        dim3 g(SEQ / 128, SEQ / 128, BATCH);
        gemm_mma<0, 1><<<g, 256, SMEMB>>>(
            qkvh, qkvl, qkvh + MS, qkvl + MS, nullptr, nullptr, nullptr,
            scores, nullptr, nullptr,
            SEQ, SEQ, DIM, (size_t)SEQ * DIM, (size_t)SEQ * DIM, (size_t)SEQ * SEQ);
    }

    // (4) transpose V -> [D][S] per batch
    {
        dim3 g(SEQ / 32, DIM / 32, BATCH);
        vtrans_kernel<<<g, 256>>>(qkvh + 2 * MS, qkvl + 2 * MS, vth, vtl);
    }

    // (5) softmax -> P (fp16, hi only)
    softmax_rows_kernel<<<BATCH * SEQ, 256>>>(scores, ph);

    // (6) out: per batch O = P @ V, 2-term (A = P hi only; B = V^T hi/lo)
    {
        dim3 g(DIM / 128, SEQ / 128, BATCH);
        gemm_mma<0, 0><<<g, 256, SMEMB>>>(
            ph, nullptr, vth, vtl, nullptr, nullptr, nullptr,
            out, nullptr, nullptr,
            SEQ, DIM, SEQ, (size_t)SEQ * SEQ, (size_t)DIM * SEQ, (size_t)SEQ * DIM);
    }
}

// round 14
// speedup vs baseline: 2.9343x; 1.0030x over previous
#include <cuda_runtime.h>
#include <cuda_fp16.h>
#include <stdint.h>

// ---------------- problem constants ----------------
#define BATCH 8
#define SEQ   2048
#define DIM   512

// ---------------- scratch (device globals; no allocs allowed) ----------------
__device__ __align__(256) float g_scores[(size_t)BATCH * SEQ * SEQ];            // 134 MB
__device__ __align__(256) __half g_xh[(size_t)BATCH * SEQ * DIM];
__device__ __align__(256) __half g_xl[(size_t)BATCH * SEQ * DIM];
__device__ __align__(256) __half g_wth[3ULL * DIM * DIM];                       // (W*256)^T split
__device__ __align__(256) __half g_wtl[3ULL * DIM * DIM];
__device__ __align__(256) __half g_qkvh[3ULL * BATCH * SEQ * DIM];
__device__ __align__(256) __half g_qkvl[3ULL * BATCH * SEQ * DIM];
__device__ __align__(256) __half g_vth[(size_t)BATCH * DIM * SEQ];              // V^T
__device__ __align__(256) __half g_vtl[(size_t)BATCH * DIM * SEQ];
__device__ __align__(256) __half g_ph[(size_t)BATCH * SEQ * SEQ];               // P (hi only), 67 MB

// ---------------- asm helpers (base-target safe: sm_80+) ----------------
__device__ __forceinline__ uint32_t smem_u32(const void* p) {
    uint32_t a;
    asm("{ .reg .u64 t; cvta.to.shared.u64 t, %1; cvt.u32.u64 %0, t; }" : "=r"(a) : "l"(p));
    return a;
}
#define CP16(sm, gp) \
    asm volatile("cp.async.cg.shared.global [%0], [%1], 16;" :: "r"(sm), "l"(gp))
#define CPCOMMIT() asm volatile("cp.async.commit_group;" ::: "memory")
#define CPWAIT0()  asm volatile("cp.async.wait_group 0;" ::: "memory")

__device__ __forceinline__ void ldsm_x4(uint32_t& r0, uint32_t& r1, uint32_t& r2, uint32_t& r3,
                                        uint32_t addr) {
    asm volatile("ldmatrix.sync.aligned.m8n8.x4.shared.b16 {%0,%1,%2,%3}, [%4];"
                 : "=r"(r0), "=r"(r1), "=r"(r2), "=r"(r3) : "r"(addr));
}
__device__ __forceinline__ void mma16816(float* c, const uint32_t* a, uint32_t b0, uint32_t b1) {
    asm volatile("mma.sync.aligned.m16n8k16.row.col.f32.f16.f16.f32 "
                 "{%0,%1,%2,%3}, {%4,%5,%6,%7}, {%8,%9}, {%0,%1,%2,%3};"
                 : "+f"(c[0]), "+f"(c[1]), "+f"(c[2]), "+f"(c[3])
                 : "r"(a[0]), "r"(a[1]), "r"(a[2]), "r"(a[3]), "r"(b0), "r"(b1));
}

__device__ __forceinline__ uint32_t pack2h(float a, float b) {
    __half2 h = __floats2half2_rn(a, b);
    return *(uint32_t*)&h;
}

// ---------------- GEMM geometry ----------------
// CTA tile 128x128x32, 8 warps: warp grid 2(m) x 4(n), warp tile 64x32.
// smem row = 32 halfs (64B) padded to 40 halfs (80B) -> conflict-free ldmatrix.
#define ROWH   40
#define TILEB  (128 * ROWH * 2)      // 10240 B per tile
#define STAGEB (4 * TILEB)           // Ah, Al, Bh, Bl
#define SMEMB  (2 * STAGEB)          // double-buffered: 81920 B

// one 128x32 half tile via cp.async 16B
__device__ __forceinline__ void load_tile(uint32_t sm,
    const __half* __restrict__ g, int ld, int tid)
{
#pragma unroll
    for (int j = 0; j < 2; j++) {
        int i   = j * 256 + tid;
        int row = i >> 2;
        int c   = i & 3;
        CP16(sm + (uint32_t)(row * 80 + c * 16),
             (const char*)(g + (size_t)row * ld) + c * 16);
    }
}

// OUTMODE 0: write fp32 C.  OUTMODE 1: scale 1/256 + bias, write half hi/lo split.
// ALO 1: 3-term (A hi/lo).  ALO 0: 2-term (A hi only; Al_ ignored).
// A: [M,K] K-major half.  B: [N,K] K-major half hi/lo.  C = A * B^T.
template<int OUTMODE, int ALO>
__global__ __launch_bounds__(256, 2)
void gemm_mma(const __half* __restrict__ Ah_, const __half* __restrict__ Al_,
              const __half* __restrict__ Bh_, const __half* __restrict__ Bl_,
              const float* __restrict__ b0p, const float* __restrict__ b1p,
              const float* __restrict__ b2p,
              float* __restrict__ C_, __half* __restrict__ Oh_,
              __half* __restrict__ Ol_,
              int M, int N, int K, size_t sA, size_t sB, size_t sC)
{
    extern __shared__ char smem[];
    const uint32_t sb = smem_u32(smem);
    const int tid = threadIdx.x, wid = tid >> 5, lane = tid & 31;
    const int z = blockIdx.z;

    const __half* Ah = Ah_ + (size_t)z * sA;
    const __half* Al = ALO ? (Al_ + (size_t)z * sA) : nullptr;
    const __half* Bh = Bh_ + (size_t)z * sB;
    const __half* Bl = Bl_ + (size_t)z * sB;

    const int m0 = blockIdx.y * 128;
    const int n0 = blockIdx.x * 128;
    const int wm = wid >> 2;      // 0..1
    const int wn = wid & 3;       // 0..3

    float acc[4][4][4];
#pragma unroll
    for (int a = 0; a < 4; a++)
#pragma unroll
        for (int b = 0; b < 4; b++)
#pragma unroll
            for (int c = 0; c < 4; c++) acc[a][b][c] = 0.0f;

    // ldmatrix lane decode
    const int blk = lane >> 3, r8 = lane & 7;
    const int arow = (blk & 1) * 8 + r8, ach = blk >> 1;
    const int brow = (blk >> 1) * 8 + r8, bch = blk & 1;

    // prefetch stage 0
    load_tile(sb, Ah + (size_t)m0 * K, K, tid);
    if (ALO) load_tile(sb + TILEB, Al + (size_t)m0 * K, K, tid);
    load_tile(sb + 2 * TILEB, Bh + (size_t)n0 * K, K, tid);
    load_tile(sb + 3 * TILEB, Bl + (size_t)n0 * K, K, tid);
    CPCOMMIT();

    const int niter = K / 32;
    for (int it = 0; it < niter; it++) {
        CPWAIT0();
        __syncthreads();

        if (it + 1 < niter) {
            const uint32_t nb = sb + ((it + 1) & 1) * STAGEB;
            const int k0 = (it + 1) * 32;
            load_tile(nb, Ah + (size_t)m0 * K + k0, K, tid);
            if (ALO) load_tile(nb + TILEB, Al + (size_t)m0 * K + k0, K, tid);
            load_tile(nb + 2 * TILEB, Bh + (size_t)n0 * K + k0, K, tid);
            load_tile(nb + 3 * TILEB, Bl + (size_t)n0 * K + k0, K, tid);
            CPCOMMIT();
        }

        const uint32_t base = sb + (it & 1) * STAGEB;
        const uint32_t aH = base, aL = base + TILEB, bH = base + 2 * TILEB, bL = base + 3 * TILEB;

#pragma unroll
        for (int ks = 0; ks < 2; ks++) {
            uint32_t ahf[4][4], alf[4][4], bhf[2][4], blf[2][4];
            // ---- load hi A frags + all B frags ----
#pragma unroll
            for (int mi = 0; mi < 4; mi++) {
                uint32_t off = (uint32_t)((wm * 64 + mi * 16 + arow) * 80 + (ks * 2 + ach) * 16);
                ldsm_x4(ahf[mi][0], ahf[mi][1], ahf[mi][2], ahf[mi][3], aH + off);
            }
#pragma unroll
            for (int n2 = 0; n2 < 2; n2++) {
                uint32_t off = (uint32_t)((wn * 32 + n2 * 16 + brow) * 80 + (ks * 2 + bch) * 16);
                ldsm_x4(bhf[n2][0], bhf[n2][1], bhf[n2][2], bhf[n2][3], bH + off);
                ldsm_x4(blf[n2][0], blf[n2][1], blf[n2][2], blf[n2][3], bL + off);
            }
            // ---- term 1: ah*bh (16 independent MMAs, no RAW chains) ----
#pragma unroll
            for (int mi = 0; mi < 4; mi++)
#pragma unroll
                for (int ni = 0; ni < 4; ni++) {
                    const int n2 = ni >> 1, p = (ni & 1) * 2;
                    mma16816(acc[mi][ni], ahf[mi], bhf[n2][p], bhf[n2][p + 1]);
                }
            // ---- load lo A frags (latency hides under term 2) ----
            if (ALO) {
#pragma unroll
                for (int mi = 0; mi < 4; mi++) {
                    uint32_t off = (uint32_t)((wm * 64 + mi * 16 + arow) * 80 + (ks * 2 + ach) * 16);
                    ldsm_x4(alf[mi][0], alf[mi][1], alf[mi][2], alf[mi][3], aL + off);
                }
            }
            // ---- term 2: ah*bl ----
#pragma unroll
            for (int mi = 0; mi < 4; mi++)
#pragma unroll
                for (int ni = 0; ni < 4; ni++) {
                    const int n2 = ni >> 1, p = (ni & 1) * 2;
                    mma16816(acc[mi][ni], ahf[mi], blf[n2][p], blf[n2][p + 1]);
                }
            // ---- term 3: al*bh ----
            if (ALO) {
#pragma unroll
                for (int mi = 0; mi < 4; mi++)
#pragma unroll
                    for (int ni = 0; ni < 4; ni++) {
                        const int n2 = ni >> 1, p = (ni & 1) * 2;
                        mma16816(acc[mi][ni], alf[mi], bhf[n2][p], bhf[n2][p + 1]);
                    }
            }
        }
    }

    // ---- epilogue ----
    const int g  = lane >> 2;
    const int c2 = (lane & 3) * 2;
#pragma unroll
    for (int mi = 0; mi < 4; mi++) {
        const int r1 = m0 + wm * 64 + mi * 16 + g;
        const int r2 = r1 + 8;
#pragma unroll
        for (int ni = 0; ni < 4; ni++) {
            const int col = n0 + wn * 32 + ni * 8 + c2;
            if (OUTMODE == 0) {
                float* C = C_ + (size_t)z * sC;
                *(float2*)(C + (size_t)r1 * N + col) = make_float2(acc[mi][ni][0], acc[mi][ni][1]);
                *(float2*)(C + (size_t)r2 * N + col) = make_float2(acc[mi][ni][2], acc[mi][ni][3]);
            } else {
                const float* bias = (z == 0) ? b0p : (z == 1) ? b1p : b2p;
                const float s = 0.00390625f;   // 1/256 compensates W*256 pre-scale
                float v0 = acc[mi][ni][0] * s + bias[col];
                float v1 = acc[mi][ni][1] * s + bias[col + 1];
                float v2 = acc[mi][ni][2] * s + bias[col];
                float v3 = acc[mi][ni][3] * s + bias[col + 1];
                float h0 = __half2float(__float2half_rn(v0));
                float h1 = __half2float(__float2half_rn(v1));
                float h2 = __half2float(__float2half_rn(v2));
                float h3 = __half2float(__float2half_rn(v3));
                __half* Oh = Oh_ + (size_t)z * sC;
                __half* Ol = Ol_ + (size_t)z * sC;
                *(uint32_t*)(Oh + (size_t)r1 * N + col) = pack2h(h0, h1);
                *(uint32_t*)(Oh + (size_t)r2 * N + col) = pack2h(h2, h3);
                *(uint32_t*)(Ol + (size_t)r1 * N + col) = pack2h(v0 - h0, v1 - h1);
                *(uint32_t*)(Ol + (size_t)r2 * N + col) = pack2h(v2 - h2, v3 - h3);
            }
        }
    }
}

// ---------------- prep: split X into fp16 hi/lo ----------------
__global__ __launch_bounds__(256)
void split_x_kernel(const float* __restrict__ x, __half* __restrict__ h,
                    __half* __restrict__ l)
{
    size_t i = (size_t)blockIdx.x * 256 + threadIdx.x;
    float4 v = ((const float4*)x)[i];
    float vv[4] = {v.x, v.y, v.z, v.w};
    float hi[4], lo[4];
#pragma unroll
    for (int t = 0; t < 4; t++) {
        __half hb = __float2half_rn(vv[t]);
        hi[t] = __half2float(hb);
        lo[t] = vv[t] - hi[t];
    }
    ((uint2*)h)[i] = make_uint2(pack2h(hi[0], hi[1]), pack2h(hi[2], hi[3]));
    ((uint2*)l)[i] = make_uint2(pack2h(lo[0], lo[1]), pack2h(lo[2], lo[3]));
}

// ---------------- prep: transpose + split (W*256) x3 ----------------
__global__ __launch_bounds__(256)
void wtrans_kernel(const float* __restrict__ Wq, const float* __restrict__ Wk,
                   const float* __restrict__ Wv,
                   __half* __restrict__ th, __half* __restrict__ tl)
{
    __shared__ float t[32][33];
    const int z = blockIdx.z;
    const float* W = (z == 0) ? Wq : (z == 1) ? Wk : Wv;
    const int u0 = blockIdx.x * 32, d0 = blockIdx.y * 32;
    const int tx = threadIdx.x & 31, ty = threadIdx.x >> 5;
#pragma unroll
    for (int k = 0; k < 32; k += 8)
        t[ty + k][tx] = W[(size_t)(d0 + ty + k) * DIM + u0 + tx];
    __syncthreads();
    __half* oh = th + (size_t)z * DIM * DIM;
    __half* ol = tl + (size_t)z * DIM * DIM;
#pragma unroll
    for (int k = 0; k < 32; k += 8) {
        float v = t[tx][ty + k] * 256.0f;      // pre-scale: keeps lo-limb normal fp16
        __half hb = __float2half_rn(v);
        float lo = v - __half2float(hb);
        oh[(size_t)(u0 + ty + k) * DIM + d0 + tx] = hb;
        ol[(size_t)(u0 + ty + k) * DIM + d0 + tx] = __float2half_rn(lo);
    }
}

// ---------------- prep: transpose V (per batch [S][D] -> [D][S]) hi/lo ----------------
__global__ __launch_bounds__(256)
void vtrans_kernel(const __half* __restrict__ vh, const __half* __restrict__ vl,
                   __half* __restrict__ oth, __half* __restrict__ otl)
{
    __shared__ __half th[32][33];
    __shared__ __half tl2[32][33];
    const int b = blockIdx.z;
    const int s0 = blockIdx.x * 32, d0 = blockIdx.y * 32;
    const __half* ih = vh + (size_t)b * SEQ * DIM;
    const __half* il = vl + (size_t)b * SEQ * DIM;
    const int tx = threadIdx.x & 31, ty = threadIdx.x >> 5;
#pragma unroll
    for (int k = 0; k < 32; k += 8) {
        th[ty + k][tx]  = ih[(size_t)(s0 + ty + k) * DIM + d0 + tx];
        tl2[ty + k][tx] = il[(size_t)(s0 + ty + k) * DIM + d0 + tx];
    }
    __syncthreads();
    __half* oh = oth + (size_t)b * DIM * SEQ;
    __half* ol = otl + (size_t)b * DIM * SEQ;
#pragma unroll
    for (int k = 0; k < 32; k += 8) {
        oh[(size_t)(d0 + ty + k) * SEQ + s0 + tx] = th[tx][ty + k];
        ol[(size_t)(d0 + ty + k) * SEQ + s0 + tx] = tl2[tx][ty + k];
    }
}

// ---------------- softmax: fp32 scores -> fp16 P (hi only) ----------------
__global__ __launch_bounds__(256)
void softmax_rows_kernel(const float* __restrict__ S, __half* __restrict__ Ph)
{
    size_t row = blockIdx.x;
    const float4* p4 = (const float4*)(S + row * (size_t)SEQ);
    const int t = threadIdx.x;

    float4 v0 = p4[t];
    float4 v1 = p4[t + 256];

    float lmax = fmaxf(fmaxf(fmaxf(v0.x, v0.y), fmaxf(v0.z, v0.w)),
                       fmaxf(fmaxf(v1.x, v1.y), fmaxf(v1.z, v1.w)));
#pragma unroll
    for (int o = 16; o > 0; o >>= 1)
        lmax = fmaxf(lmax, __shfl_xor_sync(0xffffffffu, lmax, o));

    __shared__ float sm_max[8];
    __shared__ float sm_sum[8];
    if ((t & 31) == 0) sm_max[t >> 5] = lmax;
    __syncthreads();
    float m = sm_max[0];
#pragma unroll
    for (int i = 1; i < 8; i++) m = fmaxf(m, sm_max[i]);

    v0.x = __expf(v0.x - m); v0.y = __expf(v0.y - m);
    v0.z = __expf(v0.z - m); v0.w = __expf(v0.w - m);
    v1.x = __expf(v1.x - m); v1.y = __expf(v1.y - m);
    v1.z = __expf(v1.z - m); v1.w = __expf(v1.w - m);

    float lsum = (v0.x + v0.y + v0.z + v0.w) + (v1.x + v1.y + v1.z + v1.w);
#pragma unroll
    for (int o = 16; o > 0; o >>= 1)
        lsum += __shfl_xor_sync(0xffffffffu, lsum, o);
    if ((t & 31) == 0) sm_sum[t >> 5] = lsum;
    __syncthreads();
    float s = 0.0f;
#pragma unroll
    for (int i = 0; i < 8; i++) s += sm_sum[i];

    float inv = 1.0f / s;
    uint2* oh = (uint2*)(Ph + row * (size_t)SEQ);
    oh[t]       = make_uint2(pack2h(v0.x * inv, v0.y * inv), pack2h(v0.z * inv, v0.w * inv));
    oh[t + 256] = make_uint2(pack2h(v1.x * inv, v1.y * inv), pack2h(v1.z * inv, v1.w * inv));
}

// ---------------- launcher ----------------
extern "C" void kernel_launch(void* const* d_in, const int* in_sizes, int n_in,
                              void* d_out, int out_size)
{
    const float* x  = (const float*)d_in[0];
    const float* Wq = (const float*)d_in[1];
    const float* bq = (const float*)d_in[2];
    const float* Wk = (const float*)d_in[3];
    const float* bk = (const float*)d_in[4];
    const float* Wv = (const float*)d_in[5];
    const float* bv = (const float*)d_in[6];
    float* out = (float*)d_out;

    float* scores = nullptr;
    __half *xh, *xl, *wth, *wtl, *qkvh, *qkvl, *vth, *vtl, *ph;
    cudaGetSymbolAddress((void**)&scores, g_scores);
    cudaGetSymbolAddress((void**)&xh, g_xh);
    cudaGetSymbolAddress((void**)&xl, g_xl);
    cudaGetSymbolAddress((void**)&wth, g_wth);
    cudaGetSymbolAddress((void**)&wtl, g_wtl);
    cudaGetSymbolAddress((void**)&qkvh, g_qkvh);
    cudaGetSymbolAddress((void**)&qkvl, g_qkvl);
    cudaGetSymbolAddress((void**)&vth, g_vth);
    cudaGetSymbolAddress((void**)&vtl, g_vtl);
    cudaGetSymbolAddress((void**)&ph, g_ph);

    cudaFuncSetAttribute(gemm_mma<0, 1>, cudaFuncAttributeMaxDynamicSharedMemorySize, SMEMB);
    cudaFuncSetAttribute(gemm_mma<1, 1>, cudaFuncAttributeMaxDynamicSharedMemorySize, SMEMB);
    cudaFuncSetAttribute(gemm_mma<0, 0>, cudaFuncAttributeMaxDynamicSharedMemorySize, SMEMB);

    const int    Mx = BATCH * SEQ;                 // 16384
    const size_t MS = (size_t)BATCH * SEQ * DIM;   // per-matrix split size

    // (0) split X, (1) transpose+split W*256
    split_x_kernel<<<(Mx * DIM) / 4 / 256, 256>>>(x, xh, xl);
    {
        dim3 g(DIM / 32, DIM / 32, 3);
        wtrans_kernel<<<g, 256>>>(Wq, Wk, Wv, wth, wtl);
    }

    // (2) QKV projections: A = X (stride 0), B = (W*256)^T; out split + bias, 3-term
    {
        dim3 g(DIM / 128, Mx / 128, 3);
        gemm_mma<1, 1><<<g, 256, SMEMB>>>(
            xh, xl, wth, wtl, bq, bk, bv,
            nullptr, qkvh, qkvl,
            Mx, DIM, DIM, 0, (size_t)DIM * DIM, MS);
    }

    // (3) scores: per batch S = Q @ K^T, 3-term   <-- ncu lands here (launch index 3)
    {
        dim3 g(SEQ / 128, SEQ / 128, BATCH);
        gemm_mma<0, 1><<<g, 256, SMEMB>>>(
            qkvh, qkvl, qkvh + MS, qkvl + MS, nullptr, nullptr, nullptr,
            scores, nullptr, nullptr,
            SEQ, SEQ, DIM, (size_t)SEQ * DIM, (size_t)SEQ * DIM, (size_t)SEQ * SEQ);
    }

    // (4) transpose V -> [D][S] per batch
    {
        dim3 g(SEQ / 32, DIM / 32, BATCH);
        vtrans_kernel<<<g, 256>>>(qkvh + 2 * MS, qkvl + 2 * MS, vth, vtl);
    }

    // (5) softmax -> P (fp16, hi only)
    softmax_rows_kernel<<<BATCH * SEQ, 256>>>(scores, ph);

    // (6) out: per batch O = P @ V, 2-term (A = P hi only; B = V^T hi/lo)
    {
        dim3 g(DIM / 128, SEQ / 128, BATCH);
        gemm_mma<0, 0><<<g, 256, SMEMB>>>(
            ph, nullptr, vth, vtl, nullptr, nullptr, nullptr,
            out, nullptr, nullptr,
            SEQ, DIM, SEQ, (size_t)SEQ * SEQ, (size_t)DIM * SEQ, (size_t)SEQ * DIM);
    }
}

// round 15
// speedup vs baseline: 2.9647x; 1.0104x over previous
#include <cuda_runtime.h>
#include <cuda_fp16.h>
#include <stdint.h>

// ---------------- problem constants ----------------
#define BATCH 8
#define SEQ   2048
#define DIM   512

// ---------------- scratch (device globals; no allocs allowed) ----------------
__device__ __align__(256) float g_scores[(size_t)BATCH * SEQ * SEQ];            // 134 MB
__device__ __align__(256) __half g_xh[(size_t)BATCH * SEQ * DIM];
__device__ __align__(256) __half g_xl[(size_t)BATCH * SEQ * DIM];
__device__ __align__(256) __half g_wth[3ULL * DIM * DIM];                       // (W*256)^T split
__device__ __align__(256) __half g_wtl[3ULL * DIM * DIM];
__device__ __align__(256) __half g_qkvh[3ULL * BATCH * SEQ * DIM];
__device__ __align__(256) __half g_qkvl[3ULL * BATCH * SEQ * DIM];
__device__ __align__(256) __half g_vth[(size_t)BATCH * DIM * SEQ];              // V^T
__device__ __align__(256) __half g_vtl[(size_t)BATCH * DIM * SEQ];
__device__ __align__(256) __half g_ph[(size_t)BATCH * SEQ * SEQ];               // P (hi only), 67 MB

// ---------------- asm helpers (base-target safe: sm_80+) ----------------
__device__ __forceinline__ uint32_t smem_u32(const void* p) {
    uint32_t a;
    asm("{ .reg .u64 t; cvta.to.shared.u64 t, %1; cvt.u32.u64 %0, t; }" : "=r"(a) : "l"(p));
    return a;
}
#define CP16(sm, gp) \
    asm volatile("cp.async.cg.shared.global [%0], [%1], 16;" :: "r"(sm), "l"(gp))
#define CPCOMMIT() asm volatile("cp.async.commit_group;" ::: "memory")
#define CPWAIT0()  asm volatile("cp.async.wait_group 0;" ::: "memory")

__device__ __forceinline__ void ldsm_x4(uint32_t& r0, uint32_t& r1, uint32_t& r2, uint32_t& r3,
                                        uint32_t addr) {
    asm volatile("ldmatrix.sync.aligned.m8n8.x4.shared.b16 {%0,%1,%2,%3}, [%4];"
                 : "=r"(r0), "=r"(r1), "=r"(r2), "=r"(r3) : "r"(addr));
}
__device__ __forceinline__ void mma16816(float* c, const uint32_t* a, uint32_t b0, uint32_t b1) {
    asm volatile("mma.sync.aligned.m16n8k16.row.col.f32.f16.f16.f32 "
                 "{%0,%1,%2,%3}, {%4,%5,%6,%7}, {%8,%9}, {%0,%1,%2,%3};"
                 : "+f"(c[0]), "+f"(c[1]), "+f"(c[2]), "+f"(c[3])
                 : "r"(a[0]), "r"(a[1]), "r"(a[2]), "r"(a[3]), "r"(b0), "r"(b1));
}

__device__ __forceinline__ uint32_t pack2h(float a, float b) {
    __half2 h = __floats2half2_rn(a, b);
    return *(uint32_t*)&h;
}

// ---------------- GEMM geometry ----------------
// CTA tile 128x128x32, 8 warps: warp grid 2(m) x 4(n), warp tile 64x32.
// smem row = 32 halfs (64B) padded to 40 halfs (80B) -> conflict-free ldmatrix.
#define ROWH   40
#define TILEB  (128 * ROWH * 2)      // 10240 B per tile
#define STAGEB (4 * TILEB)           // Ah, Al, Bh, Bl
#define SMEMB  (2 * STAGEB)          // double-buffered: 81920 B

// one 128x32 half tile via cp.async 16B
__device__ __forceinline__ void load_tile(uint32_t sm,
    const __half* __restrict__ g, int ld, int tid)
{
#pragma unroll
    for (int j = 0; j < 2; j++) {
        int i   = j * 256 + tid;
        int row = i >> 2;
        int c   = i & 3;
        CP16(sm + (uint32_t)(row * 80 + c * 16),
             (const char*)(g + (size_t)row * ld) + c * 16);
    }
}

// OUTMODE 0: write fp32 C.  OUTMODE 1: scale 1/256 + bias, write half hi/lo split.
// ALO 1: 3-term (A hi/lo).  ALO 0: 2-term (A hi only; Al_ ignored).
// A: [M,K] K-major half.  B: [N,K] K-major half hi/lo.  C = A * B^T.
template<int OUTMODE, int ALO>
__global__ __launch_bounds__(256, 2)
void gemm_mma(const __half* __restrict__ Ah_, const __half* __restrict__ Al_,
              const __half* __restrict__ Bh_, const __half* __restrict__ Bl_,
              const float* __restrict__ b0p, const float* __restrict__ b1p,
              const float* __restrict__ b2p,
              float* __restrict__ C_, __half* __restrict__ Oh_,
              __half* __restrict__ Ol_,
              int M, int N, int K, size_t sA, size_t sB, size_t sC)
{
    extern __shared__ char smem[];
    const uint32_t sb = smem_u32(smem);
    const int tid = threadIdx.x, wid = tid >> 5, lane = tid & 31;
    const int z = blockIdx.z;

    const __half* Ah = Ah_ + (size_t)z * sA;
    const __half* Al = ALO ? (Al_ + (size_t)z * sA) : nullptr;
    const __half* Bh = Bh_ + (size_t)z * sB;
    const __half* Bl = Bl_ + (size_t)z * sB;

    const int m0 = blockIdx.y * 128;
    const int n0 = blockIdx.x * 128;
    const int wm = wid >> 2;      // 0..1
    const int wn = wid & 3;       // 0..3

    float acc[4][4][4];
#pragma unroll
    for (int a = 0; a < 4; a++)
#pragma unroll
        for (int b = 0; b < 4; b++)
#pragma unroll
            for (int c = 0; c < 4; c++) acc[a][b][c] = 0.0f;

    // ldmatrix lane decode
    const int blk = lane >> 3, r8 = lane & 7;
    const int arow = (blk & 1) * 8 + r8, ach = blk >> 1;
    const int brow = (blk >> 1) * 8 + r8, bch = blk & 1;

    // prefetch stage 0
    load_tile(sb, Ah + (size_t)m0 * K, K, tid);
    if (ALO) load_tile(sb + TILEB, Al + (size_t)m0 * K, K, tid);
    load_tile(sb + 2 * TILEB, Bh + (size_t)n0 * K, K, tid);
    load_tile(sb + 3 * TILEB, Bl + (size_t)n0 * K, K, tid);
    CPCOMMIT();

    const int niter = K / 32;
    for (int it = 0; it < niter; it++) {
        CPWAIT0();
        __syncthreads();

        if (it + 1 < niter) {
            const uint32_t nb = sb + ((it + 1) & 1) * STAGEB;
            const int k0 = (it + 1) * 32;
            load_tile(nb, Ah + (size_t)m0 * K + k0, K, tid);
            if (ALO) load_tile(nb + TILEB, Al + (size_t)m0 * K + k0, K, tid);
            load_tile(nb + 2 * TILEB, Bh + (size_t)n0 * K + k0, K, tid);
            load_tile(nb + 3 * TILEB, Bl + (size_t)n0 * K + k0, K, tid);
            CPCOMMIT();
        }

        const uint32_t base = sb + (it & 1) * STAGEB;
        const uint32_t aH = base, aL = base + TILEB, bH = base + 2 * TILEB, bL = base + 3 * TILEB;

#pragma unroll
        for (int ks = 0; ks < 2; ks++) {
            // ---- B frags for this k-slice (live across the mi loop: 16 regs) ----
            uint32_t bhf[2][4], blf[2][4];
#pragma unroll
            for (int n2 = 0; n2 < 2; n2++) {
                uint32_t off = (uint32_t)((wn * 32 + n2 * 16 + brow) * 80 + (ks * 2 + bch) * 16);
                ldsm_x4(bhf[n2][0], bhf[n2][1], bhf[n2][2], bhf[n2][3], bH + off);
                ldsm_x4(blf[n2][0], blf[n2][1], blf[n2][2], blf[n2][3], bL + off);
            }
            // ---- per A-row: load frags, immediately consume (peak live ~100 regs) ----
#pragma unroll
            for (int mi = 0; mi < 4; mi++) {
                uint32_t off = (uint32_t)((wm * 64 + mi * 16 + arow) * 80 + (ks * 2 + ach) * 16);
                uint32_t ahf[4], alf[4];
                ldsm_x4(ahf[0], ahf[1], ahf[2], ahf[3], aH + off);
                if (ALO) ldsm_x4(alf[0], alf[1], alf[2], alf[3], aL + off);
#pragma unroll
                for (int ni = 0; ni < 4; ni++) {
                    const int n2 = ni >> 1, p = (ni & 1) * 2;
                    mma16816(acc[mi][ni], ahf, bhf[n2][p], bhf[n2][p + 1]);
                }
#pragma unroll
                for (int ni = 0; ni < 4; ni++) {
                    const int n2 = ni >> 1, p = (ni & 1) * 2;
                    mma16816(acc[mi][ni], ahf, blf[n2][p], blf[n2][p + 1]);
                }
                if (ALO) {
#pragma unroll
                    for (int ni = 0; ni < 4; ni++) {
                        const int n2 = ni >> 1, p = (ni & 1) * 2;
                        mma16816(acc[mi][ni], alf, bhf[n2][p], bhf[n2][p + 1]);
                    }
                }
            }
        }
    }

    // ---- epilogue ----
    const int g  = lane >> 2;
    const int c2 = (lane & 3) * 2;
#pragma unroll
    for (int mi = 0; mi < 4; mi++) {
        const int r1 = m0 + wm * 64 + mi * 16 + g;
        const int r2 = r1 + 8;
#pragma unroll
        for (int ni = 0; ni < 4; ni++) {
            const int col = n0 + wn * 32 + ni * 8 + c2;
            if (OUTMODE == 0) {
                float* C = C_ + (size_t)z * sC;
                *(float2*)(C + (size_t)r1 * N + col) = make_float2(acc[mi][ni][0], acc[mi][ni][1]);
                *(float2*)(C + (size_t)r2 * N + col) = make_float2(acc[mi][ni][2], acc[mi][ni][3]);
            } else {
                const float* bias = (z == 0) ? b0p : (z == 1) ? b1p : b2p;
                const float s = 0.00390625f;   // 1/256 compensates W*256 pre-scale
                float v0 = acc[mi][ni][0] * s + bias[col];
                float v1 = acc[mi][ni][1] * s + bias[col + 1];
                float v2 = acc[mi][ni][2] * s + bias[col];
                float v3 = acc[mi][ni][3] * s + bias[col + 1];
                float h0 = __half2float(__float2half_rn(v0));
                float h1 = __half2float(__float2half_rn(v1));
                float h2 = __half2float(__float2half_rn(v2));
                float h3 = __half2float(__float2half_rn(v3));
                __half* Oh = Oh_ + (size_t)z * sC;
                __half* Ol = Ol_ + (size_t)z * sC;
                *(uint32_t*)(Oh + (size_t)r1 * N + col) = pack2h(h0, h1);
                *(uint32_t*)(Oh + (size_t)r2 * N + col) = pack2h(h2, h3);
                *(uint32_t*)(Ol + (size_t)r1 * N + col) = pack2h(v0 - h0, v1 - h1);
                *(uint32_t*)(Ol + (size_t)r2 * N + col) = pack2h(v2 - h2, v3 - h3);
            }
        }
    }
}

// ---------------- prep: split X into fp16 hi/lo ----------------
__global__ __launch_bounds__(256)
void split_x_kernel(const float* __restrict__ x, __half* __restrict__ h,
                    __half* __restrict__ l)
{
    size_t i = (size_t)blockIdx.x * 256 + threadIdx.x;
    float4 v = ((const float4*)x)[i];
    float vv[4] = {v.x, v.y, v.z, v.w};
    float hi[4], lo[4];
#pragma unroll
    for (int t = 0; t < 4; t++) {
        __half hb = __float2half_rn(vv[t]);
        hi[t] = __half2float(hb);
        lo[t] = vv[t] - hi[t];
    }
    ((uint2*)h)[i] = make_uint2(pack2h(hi[0], hi[1]), pack2h(hi[2], hi[3]));
    ((uint2*)l)[i] = make_uint2(pack2h(lo[0], lo[1]), pack2h(lo[2], lo[3]));
}

// ---------------- prep: transpose + split (W*256) x3 ----------------
__global__ __launch_bounds__(256)
void wtrans_kernel(const float* __restrict__ Wq, const float* __restrict__ Wk,
                   const float* __restrict__ Wv,
                   __half* __restrict__ th, __half* __restrict__ tl)
{
    __shared__ float t[32][33];
    const int z = blockIdx.z;
    const float* W = (z == 0) ? Wq : (z == 1) ? Wk : Wv;
    const int u0 = blockIdx.x * 32, d0 = blockIdx.y * 32;
    const int tx = threadIdx.x & 31, ty = threadIdx.x >> 5;
#pragma unroll
    for (int k = 0; k < 32; k += 8)
        t[ty + k][tx] = W[(size_t)(d0 + ty + k) * DIM + u0 + tx];
    __syncthreads();
    __half* oh = th + (size_t)z * DIM * DIM;
    __half* ol = tl + (size_t)z * DIM * DIM;
#pragma unroll
    for (int k = 0; k < 32; k += 8) {
        float v = t[tx][ty + k] * 256.0f;      // pre-scale: keeps lo-limb normal fp16
        __half hb = __float2half_rn(v);
        float lo = v - __half2float(hb);
        oh[(size_t)(u0 + ty + k) * DIM + d0 + tx] = hb;
        ol[(size_t)(u0 + ty + k) * DIM + d0 + tx] = __float2half_rn(lo);
    }
}

// ---------------- prep: transpose V (per batch [S][D] -> [D][S]) hi/lo ----------------
__global__ __launch_bounds__(256)
void vtrans_kernel(const __half* __restrict__ vh, const __half* __restrict__ vl,
                   __half* __restrict__ oth, __half* __restrict__ otl)
{
    __shared__ __half th[32][33];
    __shared__ __half tl2[32][33];
    const int b = blockIdx.z;
    const int s0 = blockIdx.x * 32, d0 = blockIdx.y * 32;
    const __half* ih = vh + (size_t)b * SEQ * DIM;
    const __half* il = vl + (size_t)b * SEQ * DIM;
    const int tx = threadIdx.x & 31, ty = threadIdx.x >> 5;
#pragma unroll
    for (int k = 0; k < 32; k += 8) {
        th[ty + k][tx]  = ih[(size_t)(s0 + ty + k) * DIM + d0 + tx];
        tl2[ty + k][tx] = il[(size_t)(s0 + ty + k) * DIM + d0 + tx];
    }
    __syncthreads();
    __half* oh = oth + (size_t)b * DIM * SEQ;
    __half* ol = otl + (size_t)b * DIM * SEQ;
#pragma unroll
    for (int k = 0; k < 32; k += 8) {
        oh[(size_t)(d0 + ty + k) * SEQ + s0 + tx] = th[tx][ty + k];
        ol[(size_t)(d0 + ty + k) * SEQ + s0 + tx] = tl2[tx][ty + k];
    }
}

// ---------------- softmax: fp32 scores -> fp16 P (hi only) ----------------
__global__ __launch_bounds__(256)
void softmax_rows_kernel(const float* __restrict__ S, __half* __restrict__ Ph)
{
    size_t row = blockIdx.x;
    const float4* p4 = (const float4*)(S + row * (size_t)SEQ);
    const int t = threadIdx.x;

    float4 v0 = p4[t];
    float4 v1 = p4[t + 256];

    float lmax = fmaxf(fmaxf(fmaxf(v0.x, v0.y), fmaxf(v0.z, v0.w)),
                       fmaxf(fmaxf(v1.x, v1.y), fmaxf(v1.z, v1.w)));
#pragma unroll
    for (int o = 16; o > 0; o >>= 1)
        lmax = fmaxf(lmax, __shfl_xor_sync(0xffffffffu, lmax, o));

    __shared__ float sm_max[8];
    __shared__ float sm_sum[8];
    if ((t & 31) == 0) sm_max[t >> 5] = lmax;
    __syncthreads();
    float m = sm_max[0];
#pragma unroll
    for (int i = 1; i < 8; i++) m = fmaxf(m, sm_max[i]);

    v0.x = __expf(v0.x - m); v0.y = __expf(v0.y - m);
    v0.z = __expf(v0.z - m); v0.w = __expf(v0.w - m);
    v1.x = __expf(v1.x - m); v1.y = __expf(v1.y - m);
    v1.z = __expf(v1.z - m); v1.w = __expf(v1.w - m);

    float lsum = (v0.x + v0.y + v0.z + v0.w) + (v1.x + v1.y + v1.z + v1.w);
#pragma unroll
    for (int o = 16; o > 0; o >>= 1)
        lsum += __shfl_xor_sync(0xffffffffu, lsum, o);
    if ((t & 31) == 0) sm_sum[t >> 5] = lsum;
    __syncthreads();
    float s = 0.0f;
#pragma unroll
    for (int i = 0; i < 8; i++) s += sm_sum[i];

    float inv = 1.0f / s;
    uint2* oh = (uint2*)(Ph + row * (size_t)SEQ);
    oh[t]       = make_uint2(pack2h(v0.x * inv, v0.y * inv), pack2h(v0.z * inv, v0.w * inv));
    oh[t + 256] = make_uint2(pack2h(v1.x * inv, v1.y * inv), pack2h(v1.z * inv, v1.w * inv));
}

// ---------------- launcher ----------------
extern "C" void kernel_launch(void* const* d_in, const int* in_sizes, int n_in,
                              void* d_out, int out_size)
{
    const float* x  = (const float*)d_in[0];
    const float* Wq = (const float*)d_in[1];
    const float* bq = (const float*)d_in[2];
    const float* Wk = (const float*)d_in[3];
    const float* bk = (const float*)d_in[4];
    const float* Wv = (const float*)d_in[5];
    const float* bv = (const float*)d_in[6];
    float* out = (float*)d_out;

    float* scores = nullptr;
    __half *xh, *xl, *wth, *wtl, *qkvh, *qkvl, *vth, *vtl, *ph;
    cudaGetSymbolAddress((void**)&scores, g_scores);
    cudaGetSymbolAddress((void**)&xh, g_xh);
    cudaGetSymbolAddress((void**)&xl, g_xl);
    cudaGetSymbolAddress((void**)&wth, g_wth);
    cudaGetSymbolAddress((void**)&wtl, g_wtl);
    cudaGetSymbolAddress((void**)&qkvh, g_qkvh);
    cudaGetSymbolAddress((void**)&qkvl, g_qkvl);
    cudaGetSymbolAddress((void**)&vth, g_vth);
    cudaGetSymbolAddress((void**)&vtl, g_vtl);
    cudaGetSymbolAddress((void**)&ph, g_ph);

    cudaFuncSetAttribute(gemm_mma<0, 1>, cudaFuncAttributeMaxDynamicSharedMemorySize, SMEMB);
    cudaFuncSetAttribute(gemm_mma<1, 1>, cudaFuncAttributeMaxDynamicSharedMemorySize, SMEMB);
    cudaFuncSetAttribute(gemm_mma<0, 0>, cudaFuncAttributeMaxDynamicSharedMemorySize, SMEMB);

    const int    Mx = BATCH * SEQ;                 // 16384
    const size_t MS = (size_t)BATCH * SEQ * DIM;   // per-matrix split size

    // (0) split X, (1) transpose+split W*256
    split_x_kernel<<<(Mx * DIM) / 4 / 256, 256>>>(x, xh, xl);
    {
        dim3 g(DIM / 32, DIM / 32, 3);
        wtrans_kernel<<<g, 256>>>(Wq, Wk, Wv, wth, wtl);
    }

    // (2) QKV projections: A = X (stride 0), B = (W*256)^T; out split + bias, 3-term
    {
        dim3 g(DIM / 128, Mx / 128, 3);
        gemm_mma<1, 1><<<g, 256, SMEMB>>>(
            xh, xl, wth, wtl, bq, bk, bv,
            nullptr, qkvh, qkvl,
            Mx, DIM, DIM, 0, (size_t)DIM * DIM, MS);
    }

    // (3) scores: per batch S = Q @ K^T, 3-term   <-- ncu lands here (launch index 3)
    {
        dim3 g(SEQ / 128, SEQ / 128, BATCH);
        gemm_mma<0, 1><<<g, 256, SMEMB>>>(
            qkvh, qkvl, qkvh + MS, qkvl + MS, nullptr, nullptr, nullptr,
            scores, nullptr, nullptr,
            SEQ, SEQ, DIM, (size_t)SEQ * DIM, (size_t)SEQ * DIM, (size_t)SEQ * SEQ);
    }

    // (4) transpose V -> [D][S] per batch
    {
        dim3 g(SEQ / 32, DIM / 32, BATCH);
        vtrans_kernel<<<g, 256>>>(qkvh + 2 * MS, qkvl + 2 * MS, vth, vtl);
    }

    // (5) softmax -> P (fp16, hi only)
    softmax_rows_kernel<<<BATCH * SEQ, 256>>>(scores, ph);

    // (6) out: per batch O = P @ V, 2-term (A = P hi only; B = V^T hi/lo)
    {
        dim3 g(DIM / 128, SEQ / 128, BATCH);
        gemm_mma<0, 0><<<g, 256, SMEMB>>>(
            ph, nullptr, vth, vtl, nullptr, nullptr, nullptr,
            out, nullptr, nullptr,
            SEQ, DIM, SEQ, (size_t)SEQ * SEQ, (size_t)DIM * SEQ, (size_t)SEQ * DIM);
    }
}

// round 16
// speedup vs baseline: 3.4072x; 1.1493x over previous
#include <cuda_runtime.h>
#include <cuda_fp16.h>
#include <stdint.h>

// ---------------- problem constants ----------------
#define BATCH 8
#define SEQ   2048
#define DIM   512

// ---------------- scratch (device globals; no allocs allowed) ----------------
__device__ __align__(256) float g_scores[(size_t)BATCH * SEQ * SEQ];            // 134 MB
__device__ __align__(256) __half g_xh[(size_t)BATCH * SEQ * DIM];
__device__ __align__(256) __half g_xl[(size_t)BATCH * SEQ * DIM];
__device__ __align__(256) __half g_wth[3ULL * DIM * DIM];                       // (W*256)^T split
__device__ __align__(256) __half g_wtl[3ULL * DIM * DIM];
__device__ __align__(256) __half g_qkvh[3ULL * BATCH * SEQ * DIM];
__device__ __align__(256) __half g_qkvl[3ULL * BATCH * SEQ * DIM];
__device__ __align__(256) __half g_vth[(size_t)BATCH * DIM * SEQ];              // V^T (hi only)
__device__ __align__(256) __half g_ph[(size_t)BATCH * SEQ * SEQ];               // P (hi only), 67 MB

// ---------------- asm helpers (base-target safe: sm_80+) ----------------
__device__ __forceinline__ uint32_t smem_u32(const void* p) {
    uint32_t a;
    asm("{ .reg .u64 t; cvta.to.shared.u64 t, %1; cvt.u32.u64 %0, t; }" : "=r"(a) : "l"(p));
    return a;
}
#define CP16(sm, gp) \
    asm volatile("cp.async.cg.shared.global [%0], [%1], 16;" :: "r"(sm), "l"(gp))
#define CPCOMMIT() asm volatile("cp.async.commit_group;" ::: "memory")
#define CPWAIT0()  asm volatile("cp.async.wait_group 0;" ::: "memory")
#define CPWAIT2()  asm volatile("cp.async.wait_group 2;" ::: "memory")

__device__ __forceinline__ void ldsm_x4(uint32_t& r0, uint32_t& r1, uint32_t& r2, uint32_t& r3,
                                        uint32_t addr) {
    asm volatile("ldmatrix.sync.aligned.m8n8.x4.shared.b16 {%0,%1,%2,%3}, [%4];"
                 : "=r"(r0), "=r"(r1), "=r"(r2), "=r"(r3) : "r"(addr));
}
__device__ __forceinline__ void mma16816(float* c, const uint32_t* a, uint32_t b0, uint32_t b1) {
    asm volatile("mma.sync.aligned.m16n8k16.row.col.f32.f16.f16.f32 "
                 "{%0,%1,%2,%3}, {%4,%5,%6,%7}, {%8,%9}, {%0,%1,%2,%3};"
                 : "+f"(c[0]), "+f"(c[1]), "+f"(c[2]), "+f"(c[3])
                 : "r"(a[0]), "r"(a[1]), "r"(a[2]), "r"(a[3]), "r"(b0), "r"(b1));
}

__device__ __forceinline__ uint32_t pack2h(float a, float b) {
    __half2 h = __floats2half2_rn(a, b);
    return *(uint32_t*)&h;
}

// ---------------- GEMM geometry ----------------
// CTA tile 128x128x32, 8 warps: warp grid 2(m) x 4(n), warp tile 64x32.
// smem row = 32 halfs (64B) padded to 40 halfs (80B) -> conflict-free ldmatrix.
#define ROWH   40
#define TILEB  (128 * ROWH * 2)      // 10240 B per tile
#define STAGEB (4 * TILEB)           // Ah, Al, Bh, Bl
#define SMEMB  (2 * STAGEB)          // double-buffered: 81920 B

// one 128x32 half tile via cp.async 16B
__device__ __forceinline__ void load_tile(uint32_t sm,
    const __half* __restrict__ g, int ld, int tid)
{
#pragma unroll
    for (int j = 0; j < 2; j++) {
        int i   = j * 256 + tid;
        int row = i >> 2;
        int c   = i & 3;
        CP16(sm + (uint32_t)(row * 80 + c * 16),
             (const char*)(g + (size_t)row * ld) + c * 16);
    }
}

// =====================================================================
// 3-term GEMM (proj / scores).  2-stage double buffer.
// OUTMODE 0: fp32 C.  OUTMODE 1: scale 1/256 + bias, half hi/lo split.
// A: [M,K] K-major half hi/lo.  B: [N,K] K-major half hi/lo.  C = A*B^T.
// =====================================================================
template<int OUTMODE>
__global__ __launch_bounds__(256, 2)
void gemm_mma(const __half* __restrict__ Ah_, const __half* __restrict__ Al_,
              const __half* __restrict__ Bh_, const __half* __restrict__ Bl_,
              const float* __restrict__ b0p, const float* __restrict__ b1p,
              const float* __restrict__ b2p,
              float* __restrict__ C_, __half* __restrict__ Oh_,
              __half* __restrict__ Ol_,
              int M, int N, int K, size_t sA, size_t sB, size_t sC)
{
    extern __shared__ char smem[];
    const uint32_t sb = smem_u32(smem);
    const int tid = threadIdx.x, wid = tid >> 5, lane = tid & 31;
    const int z = blockIdx.z;

    const __half* Ah = Ah_ + (size_t)z * sA;
    const __half* Al = Al_ + (size_t)z * sA;
    const __half* Bh = Bh_ + (size_t)z * sB;
    const __half* Bl = Bl_ + (size_t)z * sB;

    const int m0 = blockIdx.y * 128;
    const int n0 = blockIdx.x * 128;
    const int wm = wid >> 2;
    const int wn = wid & 3;

    float acc[4][4][4];
#pragma unroll
    for (int a = 0; a < 4; a++)
#pragma unroll
        for (int b = 0; b < 4; b++)
#pragma unroll
            for (int c = 0; c < 4; c++) acc[a][b][c] = 0.0f;

    const int blk = lane >> 3, r8 = lane & 7;
    const int arow = (blk & 1) * 8 + r8, ach = blk >> 1;
    const int brow = (blk >> 1) * 8 + r8, bch = blk & 1;

    load_tile(sb, Ah + (size_t)m0 * K, K, tid);
    load_tile(sb + TILEB, Al + (size_t)m0 * K, K, tid);
    load_tile(sb + 2 * TILEB, Bh + (size_t)n0 * K, K, tid);
    load_tile(sb + 3 * TILEB, Bl + (size_t)n0 * K, K, tid);
    CPCOMMIT();

    const int niter = K / 32;
    for (int it = 0; it < niter; it++) {
        CPWAIT0();
        __syncthreads();

        if (it + 1 < niter) {
            const uint32_t nb = sb + ((it + 1) & 1) * STAGEB;
            const int k0 = (it + 1) * 32;
            load_tile(nb, Ah + (size_t)m0 * K + k0, K, tid);
            load_tile(nb + TILEB, Al + (size_t)m0 * K + k0, K, tid);
            load_tile(nb + 2 * TILEB, Bh + (size_t)n0 * K + k0, K, tid);
            load_tile(nb + 3 * TILEB, Bl + (size_t)n0 * K + k0, K, tid);
            CPCOMMIT();
        }

        const uint32_t base = sb + (it & 1) * STAGEB;
        const uint32_t aH = base, aL = base + TILEB, bH = base + 2 * TILEB, bL = base + 3 * TILEB;

#pragma unroll
        for (int ks = 0; ks < 2; ks++) {
            uint32_t bhf[2][4], blf[2][4];
#pragma unroll
            for (int n2 = 0; n2 < 2; n2++) {
                uint32_t off = (uint32_t)((wn * 32 + n2 * 16 + brow) * 80 + (ks * 2 + bch) * 16);
                ldsm_x4(bhf[n2][0], bhf[n2][1], bhf[n2][2], bhf[n2][3], bH + off);
                ldsm_x4(blf[n2][0], blf[n2][1], blf[n2][2], blf[n2][3], bL + off);
            }
#pragma unroll
            for (int mi = 0; mi < 4; mi++) {
                uint32_t off = (uint32_t)((wm * 64 + mi * 16 + arow) * 80 + (ks * 2 + ach) * 16);
                uint32_t ahf[4], alf[4];
                ldsm_x4(ahf[0], ahf[1], ahf[2], ahf[3], aH + off);
                ldsm_x4(alf[0], alf[1], alf[2], alf[3], aL + off);
#pragma unroll
                for (int ni = 0; ni < 4; ni++) {
                    const int n2 = ni >> 1, p = (ni & 1) * 2;
                    mma16816(acc[mi][ni], ahf, bhf[n2][p], bhf[n2][p + 1]);
                }
#pragma unroll
                for (int ni = 0; ni < 4; ni++) {
                    const int n2 = ni >> 1, p = (ni & 1) * 2;
                    mma16816(acc[mi][ni], ahf, blf[n2][p], blf[n2][p + 1]);
                }
#pragma unroll
                for (int ni = 0; ni < 4; ni++) {
                    const int n2 = ni >> 1, p = (ni & 1) * 2;
                    mma16816(acc[mi][ni], alf, bhf[n2][p], bhf[n2][p + 1]);
                }
            }
        }
    }

    const int g  = lane >> 2;
    const int c2 = (lane & 3) * 2;
#pragma unroll
    for (int mi = 0; mi < 4; mi++) {
        const int r1 = m0 + wm * 64 + mi * 16 + g;
        const int r2 = r1 + 8;
#pragma unroll
        for (int ni = 0; ni < 4; ni++) {
            const int col = n0 + wn * 32 + ni * 8 + c2;
            if (OUTMODE == 0) {
                float* C = C_ + (size_t)z * sC;
                *(float2*)(C + (size_t)r1 * N + col) = make_float2(acc[mi][ni][0], acc[mi][ni][1]);
                *(float2*)(C + (size_t)r2 * N + col) = make_float2(acc[mi][ni][2], acc[mi][ni][3]);
            } else {
                const float* bias = (z == 0) ? b0p : (z == 1) ? b1p : b2p;
                const float s = 0.00390625f;   // 1/256 compensates W*256 pre-scale
                float v0 = acc[mi][ni][0] * s + bias[col];
                float v1 = acc[mi][ni][1] * s + bias[col + 1];
                float v2 = acc[mi][ni][2] * s + bias[col];
                float v3 = acc[mi][ni][3] * s + bias[col + 1];
                float h0 = __half2float(__float2half_rn(v0));
                float h1 = __half2float(__float2half_rn(v1));
                float h2 = __half2float(__float2half_rn(v2));
                float h3 = __half2float(__float2half_rn(v3));
                __half* Oh = Oh_ + (size_t)z * sC;
                __half* Ol = Ol_ + (size_t)z * sC;
                *(uint32_t*)(Oh + (size_t)r1 * N + col) = pack2h(h0, h1);
                *(uint32_t*)(Oh + (size_t)r2 * N + col) = pack2h(h2, h3);
                *(uint32_t*)(Ol + (size_t)r1 * N + col) = pack2h(v0 - h0, v1 - h1);
                *(uint32_t*)(Ol + (size_t)r2 * N + col) = pack2h(v2 - h2, v3 - h3);
            }
        }
    }
}

// =====================================================================
// PV GEMM: 1-term fp16, 4-stage pipeline, wait_group 2.
// A = P [M,K] K-major half.  B = V^T [N,K] K-major half.  C = A*B^T fp32.
// stage = Ah tile + Bh tile = 20480 B; 4 stages = 81920 B.
// =====================================================================
#define PVSTG (2 * TILEB)            // 20480

__global__ __launch_bounds__(256, 2)
void pv_mma(const __half* __restrict__ Ah_, const __half* __restrict__ Bh_,
            float* __restrict__ C_,
            int M, int N, int K, size_t sA, size_t sB, size_t sC)
{
    extern __shared__ char smem[];
    const uint32_t sb = smem_u32(smem);
    const int tid = threadIdx.x, wid = tid >> 5, lane = tid & 31;
    const int z = blockIdx.z;

    const __half* Ah = Ah_ + (size_t)z * sA;
    const __half* Bh = Bh_ + (size_t)z * sB;

    const int m0 = blockIdx.y * 128;
    const int n0 = blockIdx.x * 128;
    const int wm = wid >> 2;
    const int wn = wid & 3;

    float acc[4][4][4];
#pragma unroll
    for (int a = 0; a < 4; a++)
#pragma unroll
        for (int b = 0; b < 4; b++)
#pragma unroll
            for (int c = 0; c < 4; c++) acc[a][b][c] = 0.0f;

    const int blk = lane >> 3, r8 = lane & 7;
    const int arow = (blk & 1) * 8 + r8, ach = blk >> 1;
    const int brow = (blk >> 1) * 8 + r8, bch = blk & 1;

    const int niter = K / 32;

    // prologue: fill stages 0..2
#pragma unroll
    for (int s = 0; s < 3; s++) {
        const uint32_t st = sb + s * PVSTG;
        load_tile(st, Ah + (size_t)m0 * K + s * 32, K, tid);
        load_tile(st + TILEB, Bh + (size_t)n0 * K + s * 32, K, tid);
        CPCOMMIT();
    }

    for (int it = 0; it < niter; it++) {
        CPWAIT2();            // stage `it` complete; stages it+1, it+2 may be in flight
        __syncthreads();      // all warps done reading slot (it+3)&3 (== compute of it-1)

        if (it + 3 < niter) {
            const uint32_t nb = sb + ((it + 3) & 3) * PVSTG;
            const int k0 = (it + 3) * 32;
            load_tile(nb, Ah + (size_t)m0 * K + k0, K, tid);
            load_tile(nb + TILEB, Bh + (size_t)n0 * K + k0, K, tid);
        }
        CPCOMMIT();           // empty group in tail keeps wait_group invariant

        const uint32_t base = sb + (it & 3) * PVSTG;
        const uint32_t aH = base, bH = base + TILEB;

#pragma unroll
        for (int ks = 0; ks < 2; ks++) {
            uint32_t bhf[2][4];
#pragma unroll
            for (int n2 = 0; n2 < 2; n2++) {
                uint32_t off = (uint32_t)((wn * 32 + n2 * 16 + brow) * 80 + (ks * 2 + bch) * 16);
                ldsm_x4(bhf[n2][0], bhf[n2][1], bhf[n2][2], bhf[n2][3], bH + off);
            }
#pragma unroll
            for (int mi = 0; mi < 4; mi++) {
                uint32_t off = (uint32_t)((wm * 64 + mi * 16 + arow) * 80 + (ks * 2 + ach) * 16);
                uint32_t ahf[4];
                ldsm_x4(ahf[0], ahf[1], ahf[2], ahf[3], aH + off);
#pragma unroll
                for (int ni = 0; ni < 4; ni++) {
                    const int n2 = ni >> 1, p = (ni & 1) * 2;
                    mma16816(acc[mi][ni], ahf, bhf[n2][p], bhf[n2][p + 1]);
                }
            }
        }
    }

    const int g  = lane >> 2;
    const int c2 = (lane & 3) * 2;
    float* C = C_ + (size_t)z * sC;
#pragma unroll
    for (int mi = 0; mi < 4; mi++) {
        const int r1 = m0 + wm * 64 + mi * 16 + g;
        const int r2 = r1 + 8;
#pragma unroll
        for (int ni = 0; ni < 4; ni++) {
            const int col = n0 + wn * 32 + ni * 8 + c2;
            *(float2*)(C + (size_t)r1 * N + col) = make_float2(acc[mi][ni][0], acc[mi][ni][1]);
            *(float2*)(C + (size_t)r2 * N + col) = make_float2(acc[mi][ni][2], acc[mi][ni][3]);
        }
    }
}

// ---------------- prep: split X into fp16 hi/lo ----------------
__global__ __launch_bounds__(256)
void split_x_kernel(const float* __restrict__ x, __half* __restrict__ h,
                    __half* __restrict__ l)
{
    size_t i = (size_t)blockIdx.x * 256 + threadIdx.x;
    float4 v = ((const float4*)x)[i];
    float vv[4] = {v.x, v.y, v.z, v.w};
    float hi[4], lo[4];
#pragma unroll
    for (int t = 0; t < 4; t++) {
        __half hb = __float2half_rn(vv[t]);
        hi[t] = __half2float(hb);
        lo[t] = vv[t] - hi[t];
    }
    ((uint2*)h)[i] = make_uint2(pack2h(hi[0], hi[1]), pack2h(hi[2], hi[3]));
    ((uint2*)l)[i] = make_uint2(pack2h(lo[0], lo[1]), pack2h(lo[2], lo[3]));
}

// ---------------- prep: transpose + split (W*256) x3 ----------------
__global__ __launch_bounds__(256)
void wtrans_kernel(const float* __restrict__ Wq, const float* __restrict__ Wk,
                   const float* __restrict__ Wv,
                   __half* __restrict__ th, __half* __restrict__ tl)
{
    __shared__ float t[32][33];
    const int z = blockIdx.z;
    const float* W = (z == 0) ? Wq : (z == 1) ? Wk : Wv;
    const int u0 = blockIdx.x * 32, d0 = blockIdx.y * 32;
    const int tx = threadIdx.x & 31, ty = threadIdx.x >> 5;
#pragma unroll
    for (int k = 0; k < 32; k += 8)
        t[ty + k][tx] = W[(size_t)(d0 + ty + k) * DIM + u0 + tx];
    __syncthreads();
    __half* oh = th + (size_t)z * DIM * DIM;
    __half* ol = tl + (size_t)z * DIM * DIM;
#pragma unroll
    for (int k = 0; k < 32; k += 8) {
        float v = t[tx][ty + k] * 256.0f;      // pre-scale: keeps lo-limb normal fp16
        __half hb = __float2half_rn(v);
        float lo = v - __half2float(hb);
        oh[(size_t)(u0 + ty + k) * DIM + d0 + tx] = hb;
        ol[(size_t)(u0 + ty + k) * DIM + d0 + tx] = __float2half_rn(lo);
    }
}

// ---------------- prep: transpose V hi (per batch [S][D] -> [D][S]) ----------------
__global__ __launch_bounds__(256)
void vtrans_kernel(const __half* __restrict__ vh, __half* __restrict__ oth)
{
    __shared__ __half th[32][33];
    const int b = blockIdx.z;
    const int s0 = blockIdx.x * 32, d0 = blockIdx.y * 32;
    const __half* ih = vh + (size_t)b * SEQ * DIM;
    const int tx = threadIdx.x & 31, ty = threadIdx.x >> 5;
#pragma unroll
    for (int k = 0; k < 32; k += 8)
        th[ty + k][tx] = ih[(size_t)(s0 + ty + k) * DIM + d0 + tx];
    __syncthreads();
    __half* oh = oth + (size_t)b * DIM * SEQ;
#pragma unroll
    for (int k = 0; k < 32; k += 8)
        oh[(size_t)(d0 + ty + k) * SEQ + s0 + tx] = th[tx][ty + k];
}

// ---------------- softmax: fp32 scores -> fp16 P (hi only) ----------------
__global__ __launch_bounds__(256)
void softmax_rows_kernel(const float* __restrict__ S, __half* __restrict__ Ph)
{
    size_t row = blockIdx.x;
    const float4* p4 = (const float4*)(S + row * (size_t)SEQ);
    const int t = threadIdx.x;

    float4 v0 = p4[t];
    float4 v1 = p4[t + 256];

    float lmax = fmaxf(fmaxf(fmaxf(v0.x, v0.y), fmaxf(v0.z, v0.w)),
                       fmaxf(fmaxf(v1.x, v1.y), fmaxf(v1.z, v1.w)));
#pragma unroll
    for (int o = 16; o > 0; o >>= 1)
        lmax = fmaxf(lmax, __shfl_xor_sync(0xffffffffu, lmax, o));

    __shared__ float sm_max[8];
    __shared__ float sm_sum[8];
    if ((t & 31) == 0) sm_max[t >> 5] = lmax;
    __syncthreads();
    float m = sm_max[0];
#pragma unroll
    for (int i = 1; i < 8; i++) m = fmaxf(m, sm_max[i]);

    v0.x = __expf(v0.x - m); v0.y = __expf(v0.y - m);
    v0.z = __expf(v0.z - m); v0.w = __expf(v0.w - m);
    v1.x = __expf(v1.x - m); v1.y = __expf(v1.y - m);
    v1.z = __expf(v1.z - m); v1.w = __expf(v1.w - m);

    float lsum = (v0.x + v0.y + v0.z + v0.w) + (v1.x + v1.y + v1.z + v1.w);
#pragma unroll
    for (int o = 16; o > 0; o >>= 1)
        lsum += __shfl_xor_sync(0xffffffffu, lsum, o);
    if ((t & 31) == 0) sm_sum[t >> 5] = lsum;
    __syncthreads();
    float s = 0.0f;
#pragma unroll
    for (int i = 0; i < 8; i++) s += sm_sum[i];

    float inv = 1.0f / s;
    uint2* oh = (uint2*)(Ph + row * (size_t)SEQ);
    oh[t]       = make_uint2(pack2h(v0.x * inv, v0.y * inv), pack2h(v0.z * inv, v0.w * inv));
    oh[t + 256] = make_uint2(pack2h(v1.x * inv, v1.y * inv), pack2h(v1.z * inv, v1.w * inv));
}

// ---------------- launcher ----------------
extern "C" void kernel_launch(void* const* d_in, const int* in_sizes, int n_in,
                              void* d_out, int out_size)
{
    const float* x  = (const float*)d_in[0];
    const float* Wq = (const float*)d_in[1];
    const float* bq = (const float*)d_in[2];
    const float* Wk = (const float*)d_in[3];
    const float* bk = (const float*)d_in[4];
    const float* Wv = (const float*)d_in[5];
    const float* bv = (const float*)d_in[6];
    float* out = (float*)d_out;

    float* scores = nullptr;
    __half *xh, *xl, *wth, *wtl, *qkvh, *qkvl, *vth, *ph;
    cudaGetSymbolAddress((void**)&scores, g_scores);
    cudaGetSymbolAddress((void**)&xh, g_xh);
    cudaGetSymbolAddress((void**)&xl, g_xl);
    cudaGetSymbolAddress((void**)&wth, g_wth);
    cudaGetSymbolAddress((void**)&wtl, g_wtl);
    cudaGetSymbolAddress((void**)&qkvh, g_qkvh);
    cudaGetSymbolAddress((void**)&qkvl, g_qkvl);
    cudaGetSymbolAddress((void**)&vth, g_vth);
    cudaGetSymbolAddress((void**)&ph, g_ph);

    cudaFuncSetAttribute(gemm_mma<0>, cudaFuncAttributeMaxDynamicSharedMemorySize, SMEMB);
    cudaFuncSetAttribute(gemm_mma<1>, cudaFuncAttributeMaxDynamicSharedMemorySize, SMEMB);
    cudaFuncSetAttribute(pv_mma,      cudaFuncAttributeMaxDynamicSharedMemorySize, SMEMB);

    const int    Mx = BATCH * SEQ;                 // 16384
    const size_t MS = (size_t)BATCH * SEQ * DIM;   // per-matrix split size

    // (0) split X, (1) transpose+split W*256
    split_x_kernel<<<(Mx * DIM) / 4 / 256, 256>>>(x, xh, xl);
    {
        dim3 g(DIM / 32, DIM / 32, 3);
        wtrans_kernel<<<g, 256>>>(Wq, Wk, Wv, wth, wtl);
    }

    // (2) QKV projections: A = X (stride 0), B = (W*256)^T; out split + bias, 3-term
    {
        dim3 g(DIM / 128, Mx / 128, 3);
        gemm_mma<1><<<g, 256, SMEMB>>>(
            xh, xl, wth, wtl, bq, bk, bv,
            nullptr, qkvh, qkvl,
            Mx, DIM, DIM, 0, (size_t)DIM * DIM, MS);
    }

    // (3) scores: per batch S = Q @ K^T, 3-term   <-- ncu lands here (launch index 3)
    {
        dim3 g(SEQ / 128, SEQ / 128, BATCH);
        gemm_mma<0><<<g, 256, SMEMB>>>(
            qkvh, qkvl, qkvh + MS, qkvl + MS, nullptr, nullptr, nullptr,
            scores, nullptr, nullptr,
            SEQ, SEQ, DIM, (size_t)SEQ * DIM, (size_t)SEQ * DIM, (size_t)SEQ * SEQ);
    }

    // (4) transpose V hi -> [D][S] per batch
    {
        dim3 g(SEQ / 32, DIM / 32, BATCH);
        vtrans_kernel<<<g, 256>>>(qkvh + 2 * MS, vth);
    }

    // (5) softmax -> P (fp16, hi only)
    softmax_rows_kernel<<<BATCH * SEQ, 256>>>(scores, ph);

    // (6) out: per batch O = P @ V, 1-term fp16, 4-stage pipeline
    {
        dim3 g(DIM / 128, SEQ / 128, BATCH);
        pv_mma<<<g, 256, SMEMB>>>(
            ph, vth, out,
            SEQ, DIM, SEQ, (size_t)SEQ * SEQ, (size_t)DIM * SEQ, (size_t)SEQ * DIM);
    }
}